// round 3
// baseline (speedup 1.0000x reference)
#include <cuda_runtime.h>
#include <math.h>

#define NB 8
#define AA 3
#define HH 200
#define WW 336
#define HWP (HH*WW)          // 67200
#define AHW (AA*HWP)         // 201600
#define AHW4 (AHW/4)         // 50400
#define PRE 2000
#define POST 1000
#define THR 0.7f
#define MAXOFF 4.135166556742356f
#define CAP 4096
#define NBINS 16384
#define BIN_OFF 0x8000
#define MW 32

__device__ unsigned int        g_hist[NB*NBINS];
__device__ int                 g_cnt[NB];
__device__ int                 g_thr[NB];
__device__ unsigned long long  g_cand[NB*CAP];
__device__ float4              g_boxes[NB*PRE];
__device__ float               g_sc[NB*PRE];

__device__ __forceinline__ unsigned skey(float x){
    float s = 1.0f/(1.0f + expf(-x));
    return __float_as_uint(s) | 0x80000000u;   // s > 0 -> orderable key
}

__device__ __forceinline__ bool iou_gt(float4 A, float aA, float4 B, float aB){
    float xtl = fmaxf(A.x, B.x), ytl = fmaxf(A.y, B.y);
    float xbr = fminf(A.z, B.z), ybr = fminf(A.w, B.w);
    float iw = fmaxf(xbr - xtl + 1.0f, 0.0f);
    float ih = fmaxf(ybr - ytl + 1.0f, 0.0f);
    float inter = iw * ih;
    float denom = aA + aB - inter;
    if (inter > 0.6f * denom)            // conservative prescreen
        return inter / denom > THR;      // exact (matches reference)
    return false;
}

__global__ void k_zero(){
    int i = blockIdx.x*blockDim.x + threadIdx.x;
    if (i < NB*NBINS) g_hist[i] = 0u;
    if (i < NB) g_cnt[i] = 0;
}

__global__ void k_hist(const float4* __restrict__ logits){
    int t = blockIdx.x*blockDim.x + threadIdx.x;
    int n = blockIdx.y;
    if (t >= AHW4) return;
    float4 v = logits[(size_t)n*AHW4 + t];
    atomicAdd(&g_hist[n*NBINS + (int)((skey(v.x)>>16) - BIN_OFF)], 1u);
    atomicAdd(&g_hist[n*NBINS + (int)((skey(v.y)>>16) - BIN_OFF)], 1u);
    atomicAdd(&g_hist[n*NBINS + (int)((skey(v.z)>>16) - BIN_OFF)], 1u);
    atomicAdd(&g_hist[n*NBINS + (int)((skey(v.w)>>16) - BIN_OFF)], 1u);
}

__global__ void k_thresh(){
    int n = blockIdx.x;
    int tid = threadIdx.x;
    __shared__ unsigned seg[1024];
    __shared__ int tstar;
    const uint4* hp = (const uint4*)(g_hist + n*NBINS + tid*16);
    unsigned s = 0;
    #pragma unroll
    for (int k=0;k<4;k++){ uint4 v = hp[k]; s += v.x+v.y+v.z+v.w; }
    seg[tid]=s; __syncthreads();
    for (int off=1; off<1024; off<<=1){
        unsigned v = (tid+off<1024) ? seg[tid+off] : 0u;
        __syncthreads();
        seg[tid] += v;
        __syncthreads();
    }
    if (seg[tid] >= PRE && (tid==1023 || seg[tid+1] < PRE)) tstar = tid;
    __syncthreads();
    if (tid==0){
        int t = tstar;
        unsigned cum = (t < 1023) ? seg[t+1] : 0u;
        int T = t*16;
        for (int b = t*16+15; b >= t*16; b--){
            cum += g_hist[n*NBINS + b];
            if (cum >= PRE){ T = b; break; }
        }
        g_thr[n] = (T > 0) ? (T - 1) : 0;   // one-bin safety margin
    }
}

__global__ void k_gather(const float4* __restrict__ logits){
    int t = blockIdx.x*blockDim.x + threadIdx.x;
    int n = blockIdx.y;
    if (t >= AHW4) return;
    float4 v = logits[(size_t)n*AHW4 + t];
    int thr = g_thr[n];
    float vv[4] = {v.x, v.y, v.z, v.w};
    #pragma unroll
    for (int k=0;k<4;k++){
        unsigned key = skey(vv[k]);
        int bin = (int)(key>>16) - BIN_OFF;
        if (bin >= thr){
            int pos = atomicAdd(&g_cnt[n], 1);
            if (pos < CAP){
                int el = t*4 + k;
                int a = el / HWP;
                int pix = el - a*HWP;
                unsigned idx = (unsigned)(pix*AA + a);   // score-space index
                g_cand[n*CAP + pos] =
                    ((unsigned long long)key << 32) | (unsigned long long)(0xFFFFFFFFu - idx);
            }
        }
    }
}

__global__ __launch_bounds__(1024) void k_sortdecode(const float* __restrict__ regs,
                             const float* __restrict__ anchors,
                             const int*   __restrict__ sizes){
    int n = blockIdx.x;
    int tid = threadIdx.x;   // 1024 threads
    __shared__ unsigned long long s[CAP];
    int cnt = g_cnt[n]; if (cnt > CAP) cnt = CAP;
    for (int k = tid; k < CAP; k += 1024)
        s[k] = (k < cnt) ? g_cand[n*CAP + k] : 0ull;
    // bitonic sort, descending (keys unique -> deterministic)
    for (int ksz = 2; ksz <= CAP; ksz <<= 1){
        for (int j = ksz>>1; j > 0; j >>= 1){
            __syncthreads();
            #pragma unroll 1
            for (int c = tid; c < CAP/2; c += 1024){
                int lo = c & (j-1);
                int idx = ((c ^ lo) << 1) | lo;
                int p = idx | j;
                unsigned long long a = s[idx], b = s[p];
                bool desc = ((idx & ksz) == 0);
                if (desc ? (a < b) : (a > b)){ s[idx] = b; s[p] = a; }
            }
        }
    }
    __syncthreads();
    float fh = (float)sizes[n*2+0];
    float fw = (float)sizes[n*2+1];
    for (int r = tid; r < PRE; r += 1024){
        unsigned long long v = s[r];
        unsigned key = (unsigned)(v >> 32);
        unsigned idx = 0xFFFFFFFFu - (unsigned)(v & 0xFFFFFFFFull);
        float score = __uint_as_float(key ^ 0x80000000u);
        float4 anc = ((const float4*)anchors)[(size_t)n*AHW + idx];
        int a = (int)(idx % (unsigned)AA);
        int pix = (int)(idx / (unsigned)AA);
        const float* rb = regs + (size_t)n*(AA*4*HWP) + (size_t)a*4*HWP + pix;
        float r0 = rb[0];
        float r1 = rb[HWP];
        float r2 = rb[2*HWP];
        float r3 = rb[3*HWP];
        float ws = anc.z - anc.x + 1.0f;
        float hs = anc.w - anc.y + 1.0f;
        float xc = anc.x + 0.5f*ws;
        float yc = anc.y + 0.5f*hs;
        float dw = fminf(r2, MAXOFF);
        float dh = fminf(r3, MAXOFF);
        xc = xc + r0*ws;
        yc = yc + r1*hs;
        ws = ws * expf(dw);
        hs = hs * expf(dh);
        float x1 = xc - 0.5f*ws;
        float y1 = yc - 0.5f*hs;
        float x2 = xc + 0.5f*ws - 1.0f;
        float y2 = yc + 0.5f*hs - 1.0f;
        x1 = fminf(fmaxf(x1, 0.0f), fw - 1.0f);
        y1 = fminf(fmaxf(y1, 0.0f), fh - 1.0f);
        x2 = fminf(fmaxf(x2, 0.0f), fw - 1.0f);
        y2 = fminf(fmaxf(y2, 0.0f), fh - 1.0f);
        g_boxes[n*PRE + r] = make_float4(x1,y1,x2,y2);
        g_sc[n*PRE + r] = score;
    }
}

// Fused NMS: lazy IoU + serial chain, one block per batch.
__global__ __launch_bounds__(1024) void k_nms(float* __restrict__ out){
    int n = blockIdx.x;
    int tid = threadIdx.x;
    __shared__ float4 sb[2048];
    __shared__ float  sa[2048];
    __shared__ __align__(8) unsigned char rm[2048];
    __shared__ unsigned long long dw[64];
    __shared__ unsigned long long sh_w0, sh_alive;
    __shared__ unsigned b32[64];
    __shared__ unsigned long long kwv[32];
    __shared__ int kb[33];

    for (int k = tid; k < 2048; k += 1024){
        float4 b = (k < PRE) ? g_boxes[n*PRE + k] : make_float4(0.f,0.f,-1.f,-1.f);
        sb[k] = b;
        sa[k] = (b.z - b.x + 1.0f) * (b.w - b.y + 1.0f);
        rm[k] = (k < PRE) ? 0 : 1;
    }
    __syncthreads();

    for (int blk = 0; blk < MW; blk++){
        int base = blk*64;
        // Phase A: 64x64 diagonal IoU tile -> dw[r]
        int r = tid >> 4, q = tid & 15;
        float4 br = sb[base + r];
        float  ar = sa[base + r];
        unsigned long long bits = 0ull;
        #pragma unroll
        for (int jj = 0; jj < 4; jj++){
            int j = jj*16 + q;
            if (j > r){
                if (iou_gt(br, ar, sb[base + j], sa[base + j]))
                    bits |= (1ull << j);
            }
        }
        bits |= __shfl_xor_sync(0xFFFFFFFFu, bits, 8, 16);
        bits |= __shfl_xor_sync(0xFFFFFFFFu, bits, 4, 16);
        bits |= __shfl_xor_sync(0xFFFFFFFFu, bits, 2, 16);
        bits |= __shfl_xor_sync(0xFFFFFFFFu, bits, 1, 16);
        if (q == 0) dw[r] = bits;
        __syncthreads();
        // Phase B: serial chain (tid 0)
        if (tid == 0){
            const unsigned long long* rp = (const unsigned long long*)&rm[base];
            unsigned long long w0 = 0ull;
            #pragma unroll
            for (int k = 0; k < 8; k++){
                unsigned long long x = rp[k] & 0x0101010101010101ull;
                w0 |= ((x * 0x0102040810204080ull) >> 56) << (8*k);
            }
            unsigned long long alive = 0ull;
            #pragma unroll
            for (int rr = 0; rr < 64; rr++){
                unsigned long long m = dw[rr];
                if (!((w0 >> rr) & 1ull)){ alive |= (1ull << rr); w0 |= m; }
            }
            sh_w0 = w0; sh_alive = alive;
        }
        __syncthreads();
        if (tid < 64){
            if ((sh_w0 >> tid) & 1ull) rm[base + tid] = 1;
        }
        // Phase C: forward columns, alive rows only
        unsigned long long alive = sh_alive;
        for (int c = base + 64 + tid; c < PRE; c += 1024){
            if (rm[c]) continue;
            float4 bc = sb[c]; float ac = sa[c];
            unsigned long long m = alive;
            bool sup = false;
            while (m){
                int rr = __ffsll((long long)m) - 1;
                m &= m - 1;
                if (iou_gt(sb[base + rr], sa[base + rr], bc, ac)){ sup = true; break; }
            }
            if (sup) rm[c] = 1;
        }
        __syncthreads();
    }

    // Output: stable partition (kept-in-order, then suppressed-in-order)
    #pragma unroll
    for (int half = 0; half < 2; half++){
        int i = half*1024 + tid;
        unsigned bal = __ballot_sync(0xFFFFFFFFu, rm[i] == 0);
        if ((tid & 31) == 0) b32[half*32 + (tid >> 5)] = bal;
    }
    __syncthreads();
    if (tid < 32)
        kwv[tid] = (unsigned long long)b32[2*tid] | ((unsigned long long)b32[2*tid+1] << 32);
    __syncthreads();
    if (tid == 0){
        int c = 0;
        for (int w = 0; w < 32; w++){ kb[w] = c; c += __popcll(kwv[w]); }
        kb[32] = c;
    }
    __syncthreads();
    for (int i = tid; i < PRE; i += 1024){
        int ww = i >> 6, b = i & 63;
        unsigned long long notr = kwv[ww];
        bool keep = (notr >> b) & 1ull;
        unsigned long long below = b ? (notr & ((~0ull) >> (64 - b))) : 0ull;
        int kbelow = kb[ww] + __popcll(below);
        int pos = keep ? kbelow : (kb[32] + (i - kbelow));
        if (pos < POST){
            float4 bx = sb[i];
            float sc = keep ? g_sc[n*PRE + i] : -1.0f;
            float* op = out + ((size_t)n*POST + pos)*5;
            op[0]=bx.x; op[1]=bx.y; op[2]=bx.z; op[3]=bx.w; op[4]=sc;
        }
    }
}

extern "C" void kernel_launch(void* const* d_in, const int* in_sizes, int n_in,
                              void* d_out, int out_size){
    (void)in_sizes; (void)n_in; (void)out_size;
    const float* logits  = (const float*)d_in[0];
    const float* regs    = (const float*)d_in[1];
    const float* anchors = (const float*)d_in[2];
    const int*   sizes   = (const int*)d_in[3];
    float* out = (float*)d_out;

    k_zero<<<(NB*NBINS + 255)/256, 256>>>();
    dim3 g((AHW4 + 255)/256, NB);
    k_hist<<<g, 256>>>((const float4*)logits);
    k_thresh<<<NB, 1024>>>();
    k_gather<<<g, 256>>>((const float4*)logits);
    k_sortdecode<<<NB, 1024>>>(regs, anchors, sizes);
    k_nms<<<NB, 1024>>>(out);
}

// round 4
// speedup vs baseline: 5.5883x; 5.5883x over previous
#include <cuda_runtime.h>
#include <math.h>

#define NB 8
#define AA 3
#define HH 200
#define WW 336
#define HWP (HH*WW)          // 67200
#define AHW (AA*HWP)         // 201600
#define AHW4 (AHW/4)         // 50400
#define PRE 2000
#define POST 1000
#define THR 0.7f
#define MAXOFF 4.135166556742356f
#define CAP 4096
#define NBINS 16384
#define BIN_OFF 0x8000
#define MW 32
#define ROWS_PAD 2048

__device__ unsigned int        g_hist[NB*NBINS];
__device__ int                 g_cnt[NB];
__device__ int                 g_thr[NB];
__device__ unsigned long long  g_cand[NB*CAP];
__device__ float4              g_boxes[NB*PRE];
__device__ float               g_sc[NB*PRE];
// row-major: g_mask[n][row][word], only words w >= row/64 are valid
__device__ unsigned long long  g_mask[(size_t)NB*ROWS_PAD*MW];

__device__ __forceinline__ unsigned skey(float x){
    float s = 1.0f/(1.0f + expf(-x));
    return __float_as_uint(s) | 0x80000000u;   // s > 0 -> orderable key
}

__global__ void k_zero(){
    int i = blockIdx.x*blockDim.x + threadIdx.x;
    if (i < NB*NBINS/4) ((uint4*)g_hist)[i] = make_uint4(0,0,0,0);
    if (i < NB) g_cnt[i] = 0;
}

__global__ void k_hist(const float4* __restrict__ logits){
    int n = blockIdx.y;
    int t0 = blockIdx.x*(blockDim.x*4) + threadIdx.x;
    const float4* p = logits + (size_t)n*AHW4;
    float4 v[4]; bool ok[4];
    #pragma unroll
    for (int q=0;q<4;q++){
        int t = t0 + q*256;
        ok[q] = (t < AHW4);
        if (ok[q]) v[q] = p[t];
    }
    #pragma unroll
    for (int q=0;q<4;q++){
        if (ok[q]){
            atomicAdd(&g_hist[n*NBINS + (int)((skey(v[q].x)>>16) - BIN_OFF)], 1u);
            atomicAdd(&g_hist[n*NBINS + (int)((skey(v[q].y)>>16) - BIN_OFF)], 1u);
            atomicAdd(&g_hist[n*NBINS + (int)((skey(v[q].z)>>16) - BIN_OFF)], 1u);
            atomicAdd(&g_hist[n*NBINS + (int)((skey(v[q].w)>>16) - BIN_OFF)], 1u);
        }
    }
}

__global__ void k_thresh(){
    int n = blockIdx.x;
    int tid = threadIdx.x;
    __shared__ unsigned seg[1024];
    __shared__ int tstar;
    const uint4* hp = (const uint4*)(g_hist + n*NBINS + tid*16);
    unsigned s = 0;
    #pragma unroll
    for (int k=0;k<4;k++){ uint4 v = hp[k]; s += v.x+v.y+v.z+v.w; }
    seg[tid]=s; __syncthreads();
    for (int off=1; off<1024; off<<=1){
        unsigned v = (tid+off<1024) ? seg[tid+off] : 0u;
        __syncthreads();
        seg[tid] += v;
        __syncthreads();
    }
    if (seg[tid] >= PRE && (tid==1023 || seg[tid+1] < PRE)) tstar = tid;
    __syncthreads();
    if (tid==0){
        int t = tstar;
        unsigned cum = (t < 1023) ? seg[t+1] : 0u;
        int T = t*16;
        for (int b = t*16+15; b >= t*16; b--){
            cum += g_hist[n*NBINS + b];
            if (cum >= PRE){ T = b; break; }
        }
        g_thr[n] = (T > 0) ? (T - 1) : 0;   // one-bin safety margin
    }
}

__global__ void k_gather(const float4* __restrict__ logits){
    int n = blockIdx.y;
    int t0 = blockIdx.x*(blockDim.x*4) + threadIdx.x;
    const float4* p = logits + (size_t)n*AHW4;
    int thr = g_thr[n];
    float4 v[4]; bool ok[4];
    #pragma unroll
    for (int q=0;q<4;q++){
        int t = t0 + q*256;
        ok[q] = (t < AHW4);
        if (ok[q]) v[q] = p[t];
    }
    #pragma unroll
    for (int q=0;q<4;q++){
        if (!ok[q]) continue;
        int t = t0 + q*256;
        float vv[4] = {v[q].x, v[q].y, v[q].z, v[q].w};
        #pragma unroll
        for (int k=0;k<4;k++){
            unsigned key = skey(vv[k]);
            int bin = (int)(key>>16) - BIN_OFF;
            if (bin >= thr){
                int pos = atomicAdd(&g_cnt[n], 1);
                if (pos < CAP){
                    int el = t*4 + k;
                    int a = el / HWP;
                    int pix = el - a*HWP;
                    unsigned idx = (unsigned)(pix*AA + a);   // score-space index
                    g_cand[n*CAP + pos] =
                        ((unsigned long long)key << 32) | (unsigned long long)(0xFFFFFFFFu - idx);
                }
            }
        }
    }
}

__global__ __launch_bounds__(1024) void k_sortdecode(const float* __restrict__ regs,
                             const float* __restrict__ anchors,
                             const int*   __restrict__ sizes){
    int n = blockIdx.x;
    int tid = threadIdx.x;   // 1024 threads
    __shared__ unsigned long long s[CAP];
    int cnt = g_cnt[n]; if (cnt > CAP) cnt = CAP;
    for (int k = tid; k < CAP; k += 1024)
        s[k] = (k < cnt) ? g_cand[n*CAP + k] : 0ull;
    // bitonic sort, descending (keys unique -> deterministic)
    for (int ksz = 2; ksz <= CAP; ksz <<= 1){
        for (int j = ksz>>1; j > 0; j >>= 1){
            __syncthreads();
            #pragma unroll 1
            for (int c = tid; c < CAP/2; c += 1024){
                int lo = c & (j-1);
                int idx = ((c ^ lo) << 1) | lo;
                int p = idx | j;
                unsigned long long a = s[idx], b = s[p];
                bool desc = ((idx & ksz) == 0);
                if (desc ? (a < b) : (a > b)){ s[idx] = b; s[p] = a; }
            }
        }
    }
    __syncthreads();
    float fh = (float)sizes[n*2+0];
    float fw = (float)sizes[n*2+1];
    for (int r = tid; r < PRE; r += 1024){
        unsigned long long v = s[r];
        unsigned key = (unsigned)(v >> 32);
        unsigned idx = 0xFFFFFFFFu - (unsigned)(v & 0xFFFFFFFFull);
        float score = __uint_as_float(key ^ 0x80000000u);
        float4 anc = ((const float4*)anchors)[(size_t)n*AHW + idx];
        int a = (int)(idx % (unsigned)AA);
        int pix = (int)(idx / (unsigned)AA);
        const float* rb = regs + (size_t)n*(AA*4*HWP) + (size_t)a*4*HWP + pix;
        float r0 = rb[0];
        float r1 = rb[HWP];
        float r2 = rb[2*HWP];
        float r3 = rb[3*HWP];
        float ws = anc.z - anc.x + 1.0f;
        float hs = anc.w - anc.y + 1.0f;
        float xc = anc.x + 0.5f*ws;
        float yc = anc.y + 0.5f*hs;
        float dw = fminf(r2, MAXOFF);
        float dh = fminf(r3, MAXOFF);
        xc = xc + r0*ws;
        yc = yc + r1*hs;
        ws = ws * expf(dw);
        hs = hs * expf(dh);
        float x1 = xc - 0.5f*ws;
        float y1 = yc - 0.5f*hs;
        float x2 = xc + 0.5f*ws - 1.0f;
        float y2 = yc + 0.5f*hs - 1.0f;
        x1 = fminf(fmaxf(x1, 0.0f), fw - 1.0f);
        y1 = fminf(fmaxf(y1, 0.0f), fh - 1.0f);
        x2 = fminf(fmaxf(x2, 0.0f), fw - 1.0f);
        y2 = fminf(fmaxf(y2, 0.0f), fh - 1.0f);
        g_boxes[n*PRE + r] = make_float4(x1,y1,x2,y2);
        g_sc[n*PRE + r] = score;
    }
}

// Upper-triangle tile IoU mask. grid = (528, NB), 256 threads.
__global__ void k_mask(){
    int n = blockIdx.y;
    int p = blockIdx.x;
    int ti = 0;
    while (p >= 32 - ti){ p -= 32 - ti; ti++; }
    int tj = ti + p;

    __shared__ float4 rb[64];
    __shared__ float4 cb[64];
    __shared__ float  ca[64];
    int tid = threadIdx.x;
    if (tid < 64){
        int gi = ti*64 + tid;
        rb[tid] = (gi < PRE) ? g_boxes[n*PRE + gi] : make_float4(0.f,0.f,-1.f,-1.f);
    } else if (tid < 128){
        int t = tid - 64;
        int gj = tj*64 + t;
        float4 b = (gj < PRE) ? g_boxes[n*PRE + gj] : make_float4(0.f,0.f,-1.f,-1.f);
        cb[t] = b;
        ca[t] = (b.z - b.x + 1.0f) * (b.w - b.y + 1.0f);
    }
    __syncthreads();

    int r = tid >> 2;        // 0..63
    int q = tid & 3;
    int i = ti*64 + r;
    float4 b0 = rb[r];
    float a0 = (b0.z - b0.x + 1.0f) * (b0.w - b0.y + 1.0f);

    unsigned long long w = 0ull;
    #pragma unroll 4
    for (int jj = 0; jj < 16; jj++){
        int j = jj*4 + q;            // strided -> conflict-free LDS across q
        int jg = tj*64 + j;
        if (jg < PRE && jg > i){
            float4 bj = cb[j];
            float aj = ca[j];
            float xtl = fmaxf(b0.x, bj.x), ytl = fmaxf(b0.y, bj.y);
            float xbr = fminf(b0.z, bj.z), ybr = fminf(b0.w, bj.w);
            float iw = fmaxf(xbr - xtl + 1.0f, 0.0f);
            float ih = fmaxf(ybr - ytl + 1.0f, 0.0f);
            float inter = iw * ih;
            float denom = a0 + aj - inter;
            if (inter > 0.6f * denom){           // conservative prescreen
                if (inter / denom > THR)         // exact (matches reference)
                    w |= (1ull << j);
            }
        }
    }
    w |= __shfl_xor_sync(0xFFFFFFFFu, w, 1, 4);
    w |= __shfl_xor_sync(0xFFFFFFFFu, w, 2, 4);
    if (q == 0 && i < PRE)
        g_mask[((size_t)n*ROWS_PAD + i)*MW + tj] = w;
}

#define TS 33
__global__ __launch_bounds__(512) void k_scan(float* __restrict__ out){
    int n = blockIdx.x;
    int tid = threadIdx.x;    // 512 = 16 warps
    int lane = tid & 31;
    int wrp  = tid >> 5;
    __shared__ unsigned long long remv[MW];
    __shared__ unsigned long long tile[2][64*TS];
    __shared__ unsigned long long sh_alive;
    __shared__ int kb[MW+1];
    if (tid < MW) remv[tid] = 0ull;

    // preload tile 0 (64 rows x 32 words = 2048 u64, 4 per thread)
    {
        const unsigned long long* gp = &g_mask[((size_t)n*ROWS_PAD)*MW];
        #pragma unroll
        for (int q = 0; q < 4; q++){
            int k = tid + q*512;
            tile[0][(k >> 5)*TS + (k & 31)] = gp[k];
        }
    }
    __syncthreads();

    for (int blk = 0; blk < MW; blk++){
        int cur = blk & 1, nxt = cur ^ 1;
        int base = blk*64;
        int nrows = PRE - base; if (nrows > 64) nrows = 64;

        // prefetch next tile into registers (overlaps chain + OR phase)
        unsigned long long pf[4];
        bool has_next = (blk + 1 < MW);
        if (has_next){
            const unsigned long long* gp = &g_mask[((size_t)n*ROWS_PAD + (blk+1)*64)*MW];
            #pragma unroll
            for (int q = 0; q < 4; q++) pf[q] = gp[tid + q*512];
        }

        if (tid == 0){
            unsigned long long w0 = remv[blk];
            unsigned long long alive = 0ull;
            #pragma unroll
            for (int rr = 0; rr < 64; rr++){
                if (rr < nrows){
                    unsigned long long m = tile[cur][rr*TS + blk];
                    if (!((w0 >> rr) & 1ull)){
                        alive |= (1ull << rr);
                        w0 |= m;
                    }
                }
            }
            remv[blk] = w0;
            sh_alive = alive;
        }
        __syncthreads();

        unsigned long long alive = sh_alive;
        unsigned long long acc = 0ull;
        for (int rr = wrp; rr < nrows; rr += 16){
            if ((alive >> rr) & 1ull) acc |= tile[cur][rr*TS + lane];
        }
        if (acc && lane > blk) atomicOr(&remv[lane], acc);

        if (has_next){
            #pragma unroll
            for (int q = 0; q < 4; q++){
                int k = tid + q*512;
                tile[nxt][(k >> 5)*TS + (k & 31)] = pf[q];
            }
        }
        __syncthreads();
    }

    if (tid == 0){
        int c = 0;
        for (int ww = 0; ww < MW; ww++){
            kb[ww] = c;
            unsigned long long valid = (ww == MW-1) ? 0xFFFFull : ~0ull;
            c += __popcll((~remv[ww]) & valid);
        }
        kb[MW] = c;
    }
    __syncthreads();
    // stable partition: kept (in order) then suppressed (in order) == post top_k
    for (int i = tid; i < PRE; i += 512){
        int ww = i >> 6, b = i & 63;
        unsigned long long valid = (ww == MW-1) ? 0xFFFFull : ~0ull;
        unsigned long long notr = (~remv[ww]) & valid;
        bool keep = (notr >> b) & 1ull;
        unsigned long long below = b ? (notr & ((~0ull) >> (64 - b))) : 0ull;
        int kbelow = kb[ww] + __popcll(below);
        int pos = keep ? kbelow : (kb[MW] + (i - kbelow));
        if (pos < POST){
            float4 bx = g_boxes[n*PRE + i];
            float sc = keep ? g_sc[n*PRE + i] : -1.0f;
            float* op = out + ((size_t)n*POST + pos)*5;
            op[0]=bx.x; op[1]=bx.y; op[2]=bx.z; op[3]=bx.w; op[4]=sc;
        }
    }
}

extern "C" void kernel_launch(void* const* d_in, const int* in_sizes, int n_in,
                              void* d_out, int out_size){
    (void)in_sizes; (void)n_in; (void)out_size;
    const float* logits  = (const float*)d_in[0];
    const float* regs    = (const float*)d_in[1];
    const float* anchors = (const float*)d_in[2];
    const int*   sizes   = (const int*)d_in[3];
    float* out = (float*)d_out;

    k_zero<<<(NB*NBINS/4 + 255)/256, 256>>>();
    dim3 g((AHW4 + 1023)/1024, NB);
    k_hist<<<g, 256>>>((const float4*)logits);
    k_thresh<<<NB, 1024>>>();
    k_gather<<<g, 256>>>((const float4*)logits);
    k_sortdecode<<<NB, 1024>>>(regs, anchors, sizes);
    k_mask<<<dim3(528, NB), 256>>>();
    k_scan<<<NB, 512>>>(out);
}

// round 5
// speedup vs baseline: 6.2409x; 1.1168x over previous
#include <cuda_runtime.h>
#include <math.h>

#define NB 8
#define AA 3
#define HH 200
#define WW 336
#define HWP (HH*WW)          // 67200
#define AHW (AA*HWP)         // 201600
#define AHW4 (AHW/4)         // 50400
#define PRE 2000
#define POST 1000
#define THR 0.7f
#define MAXOFF 4.135166556742356f
#define CAP 4096
#define NBINS 16384
#define BIN_OFF 0x8000
#define STATIC_BIN 16230     // bin of score 0.9 (conservative pre-gather cutoff)
#define MW 32
#define ROWS_PAD 2048

__device__ unsigned int        g_hist[NB*NBINS];
__device__ int                 g_cnt[NB];
__device__ int                 g_thr[NB];
__device__ int                 g_need[NB];
__device__ unsigned long long  g_cand[NB*CAP];
__device__ float4              g_boxes[NB*PRE];
__device__ float               g_sc[NB*PRE];
// row-major: g_mask[n][row][word], only words w >= row/64 are valid
__device__ unsigned long long  g_mask[(size_t)NB*ROWS_PAD*MW];

__device__ __forceinline__ unsigned skey(float x){
    float s = 1.0f/(1.0f + expf(-x));
    return __float_as_uint(s) | 0x80000000u;   // s > 0 -> orderable key
}

__device__ __forceinline__ void emit_cand(int n, unsigned key, int el){
    int pos = atomicAdd(&g_cnt[n], 1);
    if (pos < CAP){
        int a = el / HWP;
        int pix = el - a*HWP;
        unsigned idx = (unsigned)(pix*AA + a);     // score-space index
        g_cand[n*CAP + pos] =
            ((unsigned long long)key << 32) | (unsigned long long)(0xFFFFFFFFu - idx);
    }
}

__global__ void k_zero(){
    int i = blockIdx.x*blockDim.x + threadIdx.x;
    if (i < NB*NBINS/4) ((uint4*)g_hist)[i] = make_uint4(0,0,0,0);
    if (i < NB) g_cnt[i] = 0;
}

// hist + opportunistic gather (bin >= STATIC_BIN)
__global__ void k_hist(const float4* __restrict__ logits){
    int n = blockIdx.y;
    int t = blockIdx.x*blockDim.x + threadIdx.x;
    if (t >= AHW4) return;
    float4 v = logits[(size_t)n*AHW4 + t];
    float vv[4] = {v.x, v.y, v.z, v.w};
    #pragma unroll
    for (int k = 0; k < 4; k++){
        unsigned key = skey(vv[k]);
        int bin = (int)(key>>16) - BIN_OFF;
        atomicAdd(&g_hist[n*NBINS + bin], 1u);
        if (bin >= STATIC_BIN) emit_cand(n, key, t*4 + k);
    }
}

__global__ void k_thresh(){
    int n = blockIdx.x;
    int tid = threadIdx.x;
    __shared__ unsigned seg[1024];
    __shared__ int tstar;
    const uint4* hp = (const uint4*)(g_hist + n*NBINS + tid*16);
    unsigned s = 0;
    #pragma unroll
    for (int k=0;k<4;k++){ uint4 v = hp[k]; s += v.x+v.y+v.z+v.w; }
    seg[tid]=s; __syncthreads();
    for (int off=1; off<1024; off<<=1){
        unsigned v = (tid+off<1024) ? seg[tid+off] : 0u;
        __syncthreads();
        seg[tid] += v;
        __syncthreads();
    }
    if (seg[tid] >= PRE && (tid==1023 || seg[tid+1] < PRE)) tstar = tid;
    __syncthreads();
    if (tid==0){
        int t = tstar;
        unsigned cum = (t < 1023) ? seg[t+1] : 0u;
        int T = t*16;
        for (int b = t*16+15; b >= t*16; b--){
            cum += g_hist[n*NBINS + b];
            if (cum >= PRE){ T = b; break; }
        }
        int thrv = (T > 0) ? (T - 1) : 0;      // one-bin safety margin
        g_thr[n] = thrv;
        // fast path valid iff static pre-gather provably supersets top-2000 bins
        bool fast = (STATIC_BIN <= thrv) && (g_cnt[n] <= CAP);
        g_need[n] = fast ? 0 : 1;
        if (!fast) g_cnt[n] = 0;               // re-gather from scratch
    }
}

// fallback gather (skipped when static pre-gather sufficed)
__global__ void k_gather(const float4* __restrict__ logits){
    int n = blockIdx.y;
    if (!g_need[n]) return;
    int t = blockIdx.x*blockDim.x + threadIdx.x;
    if (t >= AHW4) return;
    float4 v = logits[(size_t)n*AHW4 + t];
    int thr = g_thr[n];
    float vv[4] = {v.x, v.y, v.z, v.w};
    #pragma unroll
    for (int k=0;k<4;k++){
        unsigned key = skey(vv[k]);
        int bin = (int)(key>>16) - BIN_OFF;
        if (bin >= thr) emit_cand(n, key, t*4 + k);
    }
}

__device__ __forceinline__ void ce_reg(unsigned long long &a, unsigned long long &b, bool desc){
    if (desc ? (a < b) : (a > b)){ unsigned long long t=a; a=b; b=t; }
}

// stages j = jmax..1 (jmax <= 64) on the 128-element block b, warp-local
__device__ __forceinline__ void reg_stages(unsigned long long r[4], int b, int lane,
                                           int ksz, int jmax){
    if (jmax >= 64){
        bool d0 = (((b*128 + 0*32 + lane) & ksz) == 0);
        bool d1 = (((b*128 + 1*32 + lane) & ksz) == 0);
        ce_reg(r[0], r[2], d0);
        ce_reg(r[1], r[3], d1);
    }
    if (jmax >= 32){
        bool d0 = (((b*128 + 0*32 + lane) & ksz) == 0);
        bool d2 = (((b*128 + 2*32 + lane) & ksz) == 0);
        ce_reg(r[0], r[1], d0);
        ce_reg(r[2], r[3], d2);
    }
    int js = (jmax < 16) ? jmax : 16;
    for (int j = js; j >= 1; j >>= 1){
        #pragma unroll
        for (int k = 0; k < 4; k++){
            unsigned long long partner = __shfl_xor_sync(0xFFFFFFFFu, r[k], j);
            int idx_low = b*128 + k*32 + (lane & ~j);
            bool desc = ((idx_low & ksz) == 0);
            bool lower = ((lane & j) == 0);
            bool take_max = (lower == desc);
            r[k] = take_max ? (r[k] > partner ? r[k] : partner)
                            : (r[k] < partner ? r[k] : partner);
        }
    }
}

__global__ __launch_bounds__(1024) void k_sortdecode(const float* __restrict__ regs,
                             const float* __restrict__ anchors,
                             const int*   __restrict__ sizes){
    int n = blockIdx.x;
    int tid = threadIdx.x;   // 1024 threads = 32 warps
    int lane = tid & 31;
    int b    = tid >> 5;     // warp id = 128-element block id
    __shared__ unsigned long long s[CAP];
    int cnt = g_cnt[n]; if (cnt > CAP) cnt = CAP;
    for (int k = tid; k < CAP; k += 1024)
        s[k] = (k < cnt) ? g_cand[n*CAP + k] : 0ull;
    __syncthreads();

    // Phase A: all ksz=2..128 stages, warp-local (registers + shfl)
    {
        unsigned long long r[4];
        #pragma unroll
        for (int k = 0; k < 4; k++) r[k] = s[b*128 + k*32 + lane];
        #pragma unroll
        for (int ksz = 2; ksz <= 128; ksz <<= 1)
            reg_stages(r, b, lane, ksz, ksz >> 1);
        #pragma unroll
        for (int k = 0; k < 4; k++) s[b*128 + k*32 + lane] = r[k];
    }
    __syncthreads();

    // Phase B: ksz = 256..4096; smem CE for j>=128, register phase for j<=64
    for (int ksz = 256; ksz <= CAP; ksz <<= 1){
        for (int j = ksz >> 1; j >= 128; j >>= 1){
            #pragma unroll 1
            for (int c = tid; c < CAP/2; c += 1024){
                int lo = c & (j-1);
                int idx = ((c ^ lo) << 1) | lo;
                int p = idx | j;
                unsigned long long a = s[idx], bb = s[p];
                bool desc = ((idx & ksz) == 0);
                if (desc ? (a < bb) : (a > bb)){ s[idx] = bb; s[p] = a; }
            }
            __syncthreads();
        }
        {
            unsigned long long r[4];
            #pragma unroll
            for (int k = 0; k < 4; k++) r[k] = s[b*128 + k*32 + lane];
            reg_stages(r, b, lane, ksz, 64);
            #pragma unroll
            for (int k = 0; k < 4; k++) s[b*128 + k*32 + lane] = r[k];
        }
        __syncthreads();
    }

    float fh = (float)sizes[n*2+0];
    float fw = (float)sizes[n*2+1];
    for (int r = tid; r < PRE; r += 1024){
        unsigned long long v = s[r];
        unsigned key = (unsigned)(v >> 32);
        unsigned idx = 0xFFFFFFFFu - (unsigned)(v & 0xFFFFFFFFull);
        float score = __uint_as_float(key ^ 0x80000000u);
        float4 anc = ((const float4*)anchors)[(size_t)n*AHW + idx];
        int a = (int)(idx % (unsigned)AA);
        int pix = (int)(idx / (unsigned)AA);
        const float* rb = regs + (size_t)n*(AA*4*HWP) + (size_t)a*4*HWP + pix;
        float r0 = rb[0];
        float r1 = rb[HWP];
        float r2 = rb[2*HWP];
        float r3 = rb[3*HWP];
        float ws = anc.z - anc.x + 1.0f;
        float hs = anc.w - anc.y + 1.0f;
        float xc = anc.x + 0.5f*ws;
        float yc = anc.y + 0.5f*hs;
        float dw = fminf(r2, MAXOFF);
        float dh = fminf(r3, MAXOFF);
        xc = xc + r0*ws;
        yc = yc + r1*hs;
        ws = ws * expf(dw);
        hs = hs * expf(dh);
        float x1 = xc - 0.5f*ws;
        float y1 = yc - 0.5f*hs;
        float x2 = xc + 0.5f*ws - 1.0f;
        float y2 = yc + 0.5f*hs - 1.0f;
        x1 = fminf(fmaxf(x1, 0.0f), fw - 1.0f);
        y1 = fminf(fmaxf(y1, 0.0f), fh - 1.0f);
        x2 = fminf(fmaxf(x2, 0.0f), fw - 1.0f);
        y2 = fminf(fmaxf(y2, 0.0f), fh - 1.0f);
        g_boxes[n*PRE + r] = make_float4(x1,y1,x2,y2);
        g_sc[n*PRE + r] = score;
    }
}

// Upper-triangle tile IoU mask. grid = (528, NB), 256 threads.
// Thread layout: rid = tid>>3 (rows rid, rid+32), q = tid&7 (8 cols each).
__global__ void k_mask(){
    int n = blockIdx.y;
    int p = blockIdx.x;
    int ti = 0;
    while (p >= 32 - ti){ p -= 32 - ti; ti++; }
    int tj = ti + p;

    __shared__ float4 rb[64];
    __shared__ float4 cb[64];
    __shared__ float  ca[64];
    int tid = threadIdx.x;
    if (tid < 64){
        int gi = ti*64 + tid;
        rb[tid] = (gi < PRE) ? g_boxes[n*PRE + gi] : make_float4(0.f,0.f,-1.f,-1.f);
    } else if (tid < 128){
        int t = tid - 64;
        int gj = tj*64 + t;
        float4 b = (gj < PRE) ? g_boxes[n*PRE + gj] : make_float4(0.f,0.f,-1.f,-1.f);
        cb[t] = b;
        ca[t] = (b.z - b.x + 1.0f) * (b.w - b.y + 1.0f);
    }
    __syncthreads();

    int rid = tid >> 3;       // 0..31
    int q   = tid & 7;
    int iA = ti*64 + rid;
    int iB = iA + 32;
    float4 bA = rb[rid];
    float4 bB = rb[rid + 32];
    float aA = (bA.z - bA.x + 1.0f) * (bA.w - bA.y + 1.0f);
    float aB = (bB.z - bB.x + 1.0f) * (bB.w - bB.y + 1.0f);

    unsigned long long wA = 0ull, wB = 0ull;
    #pragma unroll
    for (int jj = 0; jj < 8; jj++){
        int j = jj*8 + q;            // strided -> conflict-free LDS across q
        int jg = tj*64 + j;
        if (jg >= PRE) continue;
        float4 bj = cb[j];
        float aj = ca[j];
        float xtlA = fmaxf(bA.x, bj.x), ytlA = fmaxf(bA.y, bj.y);
        float xbrA = fminf(bA.z, bj.z), ybrA = fminf(bA.w, bj.w);
        float iwA = fmaxf(xbrA - xtlA + 1.0f, 0.0f);
        float ihA = fmaxf(ybrA - ytlA + 1.0f, 0.0f);
        float interA = iwA * ihA;
        float denomA = aA + aj - interA;
        if (jg > iA && interA > 0.6f * denomA)
            if (interA / denomA > THR) wA |= (1ull << j);
        float xtlB = fmaxf(bB.x, bj.x), ytlB = fmaxf(bB.y, bj.y);
        float xbrB = fminf(bB.z, bj.z), ybrB = fminf(bB.w, bj.w);
        float iwB = fmaxf(xbrB - xtlB + 1.0f, 0.0f);
        float ihB = fmaxf(ybrB - ytlB + 1.0f, 0.0f);
        float interB = iwB * ihB;
        float denomB = aB + aj - interB;
        if (jg > iB && interB > 0.6f * denomB)
            if (interB / denomB > THR) wB |= (1ull << j);
    }
    wA |= __shfl_xor_sync(0xFFFFFFFFu, wA, 1, 8);
    wA |= __shfl_xor_sync(0xFFFFFFFFu, wA, 2, 8);
    wA |= __shfl_xor_sync(0xFFFFFFFFu, wA, 4, 8);
    wB |= __shfl_xor_sync(0xFFFFFFFFu, wB, 1, 8);
    wB |= __shfl_xor_sync(0xFFFFFFFFu, wB, 2, 8);
    wB |= __shfl_xor_sync(0xFFFFFFFFu, wB, 4, 8);
    if (q == 0){
        if (iA < PRE) g_mask[((size_t)n*ROWS_PAD + iA)*MW + tj] = wA;
        if (iB < PRE) g_mask[((size_t)n*ROWS_PAD + iB)*MW + tj] = wB;
    }
}

#define TS 33
__global__ __launch_bounds__(512) void k_scan(float* __restrict__ out){
    int n = blockIdx.x;
    int tid = threadIdx.x;    // 512 = 16 warps
    int lane = tid & 31;
    int wrp  = tid >> 5;
    __shared__ unsigned long long remv[MW];
    __shared__ unsigned long long tile[2][64*TS];
    __shared__ unsigned long long sh_alive;
    __shared__ int kb[MW+1];
    if (tid < MW) remv[tid] = 0ull;

    {
        const unsigned long long* gp = &g_mask[((size_t)n*ROWS_PAD)*MW];
        #pragma unroll
        for (int q = 0; q < 4; q++){
            int k = tid + q*512;
            tile[0][(k >> 5)*TS + (k & 31)] = gp[k];
        }
    }
    __syncthreads();

    for (int blk = 0; blk < MW; blk++){
        int cur = blk & 1, nxt = cur ^ 1;
        int base = blk*64;
        int nrows = PRE - base; if (nrows > 64) nrows = 64;

        unsigned long long pf[4];
        bool has_next = (blk + 1 < MW);
        if (has_next){
            const unsigned long long* gp = &g_mask[((size_t)n*ROWS_PAD + (blk+1)*64)*MW];
            #pragma unroll
            for (int q = 0; q < 4; q++) pf[q] = gp[tid + q*512];
        }

        if (tid == 0){
            unsigned long long w0 = remv[blk];
            unsigned long long alive = 0ull;
            #pragma unroll
            for (int rr = 0; rr < 64; rr++){
                if (rr < nrows){
                    unsigned long long m = tile[cur][rr*TS + blk];
                    if (!((w0 >> rr) & 1ull)){
                        alive |= (1ull << rr);
                        w0 |= m;
                    }
                }
            }
            remv[blk] = w0;
            sh_alive = alive;
        }
        __syncthreads();

        unsigned long long alive = sh_alive;
        unsigned long long acc = 0ull;
        for (int rr = wrp; rr < nrows; rr += 16){
            if ((alive >> rr) & 1ull) acc |= tile[cur][rr*TS + lane];
        }
        if (acc && lane > blk) atomicOr(&remv[lane], acc);

        if (has_next){
            #pragma unroll
            for (int q = 0; q < 4; q++){
                int k = tid + q*512;
                tile[nxt][(k >> 5)*TS + (k & 31)] = pf[q];
            }
        }
        __syncthreads();
    }

    if (tid == 0){
        int c = 0;
        for (int ww = 0; ww < MW; ww++){
            kb[ww] = c;
            unsigned long long valid = (ww == MW-1) ? 0xFFFFull : ~0ull;
            c += __popcll((~remv[ww]) & valid);
        }
        kb[MW] = c;
    }
    __syncthreads();
    // stable partition: kept (in order) then suppressed (in order) == post top_k
    for (int i = tid; i < PRE; i += 512){
        int ww = i >> 6, b = i & 63;
        unsigned long long valid = (ww == MW-1) ? 0xFFFFull : ~0ull;
        unsigned long long notr = (~remv[ww]) & valid;
        bool keep = (notr >> b) & 1ull;
        unsigned long long below = b ? (notr & ((~0ull) >> (64 - b))) : 0ull;
        int kbelow = kb[ww] + __popcll(below);
        int pos = keep ? kbelow : (kb[MW] + (i - kbelow));
        if (pos < POST){
            float4 bx = g_boxes[n*PRE + i];
            float sc = keep ? g_sc[n*PRE + i] : -1.0f;
            float* op = out + ((size_t)n*POST + pos)*5;
            op[0]=bx.x; op[1]=bx.y; op[2]=bx.z; op[3]=bx.w; op[4]=sc;
        }
    }
}

extern "C" void kernel_launch(void* const* d_in, const int* in_sizes, int n_in,
                              void* d_out, int out_size){
    (void)in_sizes; (void)n_in; (void)out_size;
    const float* logits  = (const float*)d_in[0];
    const float* regs    = (const float*)d_in[1];
    const float* anchors = (const float*)d_in[2];
    const int*   sizes   = (const int*)d_in[3];
    float* out = (float*)d_out;

    k_zero<<<(NB*NBINS/4 + 255)/256, 256>>>();
    dim3 g((AHW4 + 255)/256, NB);
    k_hist<<<g, 256>>>((const float4*)logits);
    k_thresh<<<NB, 1024>>>();
    k_gather<<<g, 256>>>((const float4*)logits);
    k_sortdecode<<<NB, 1024>>>(regs, anchors, sizes);
    k_mask<<<dim3(528, NB), 256>>>();
    k_scan<<<NB, 512>>>(out);
}

// round 6
// speedup vs baseline: 6.4714x; 1.0369x over previous
#include <cuda_runtime.h>
#include <math.h>

#define NB 8
#define AA 3
#define HH 200
#define WW 336
#define HWP (HH*WW)          // 67200
#define AHW (AA*HWP)         // 201600
#define AHW4 (AHW/4)         // 50400
#define PRE 2000
#define POST 1000
#define THR 0.7f
#define MAXOFF 4.135166556742356f
#define CAP 4096
#define NBINS 65536
#define STATIC_BIN 49164     // logit-key bin of ln(9)=2.19722 (score 0.9)
#define MW 32
#define ROWS_PAD 2048

__device__ unsigned int        g_hist[NB*NBINS];
__device__ int                 g_cnt[NB];
__device__ int                 g_thr[NB];
__device__ int                 g_need[NB];
__device__ unsigned long long  g_cand[NB*CAP];
__device__ float4              g_boxes[NB*PRE];
__device__ float               g_sc[NB*PRE];
// row-major: g_mask[n][row][word], only words w >= row/64 are valid
__device__ unsigned long long  g_mask[(size_t)NB*ROWS_PAD*MW];

// orderable key of raw logit (monotone with sigmoid)
__device__ __forceinline__ unsigned lkey(float x){
    unsigned b = __float_as_uint(x);
    return (b & 0x80000000u) ? ~b : (b | 0x80000000u);
}

// exact reference score key (sigmoid), computed only for candidates
__device__ __forceinline__ unsigned skey(float x){
    float s = 1.0f/(1.0f + expf(-x));
    return __float_as_uint(s) | 0x80000000u;   // s > 0 -> orderable
}

__device__ __forceinline__ void emit_cand(int n, float x, int el){
    int pos = atomicAdd(&g_cnt[n], 1);
    if (pos < CAP){
        int a = el / HWP;
        int pix = el - a*HWP;
        unsigned idx = (unsigned)(pix*AA + a);     // score-space index
        g_cand[n*CAP + pos] =
            ((unsigned long long)skey(x) << 32) | (unsigned long long)(0xFFFFFFFFu - idx);
    }
}

__global__ void k_zero(){
    int i = blockIdx.x*blockDim.x + threadIdx.x;
    if (i < NB*NBINS/4) ((uint4*)g_hist)[i] = make_uint4(0,0,0,0);
    if (i < NB) g_cnt[i] = 0;
}

// hist on logit bins + opportunistic gather (bin >= STATIC_BIN)
__global__ void k_hist(const float4* __restrict__ logits){
    int n = blockIdx.y;
    int t = blockIdx.x*blockDim.x + threadIdx.x;
    if (t >= AHW4) return;
    float4 v = logits[(size_t)n*AHW4 + t];
    float vv[4] = {v.x, v.y, v.z, v.w};
    #pragma unroll
    for (int k = 0; k < 4; k++){
        unsigned bin = lkey(vv[k]) >> 16;
        atomicAdd(&g_hist[n*NBINS + bin], 1u);
        if (bin >= STATIC_BIN) emit_cand(n, vv[k], t*4 + k);
    }
}

__global__ void k_thresh(){
    int n = blockIdx.x;
    int tid = threadIdx.x;
    __shared__ unsigned seg[1024];
    __shared__ int tstar;
    const uint4* hp = (const uint4*)(g_hist + n*NBINS + tid*64);
    unsigned s = 0;
    #pragma unroll
    for (int k=0;k<16;k++){ uint4 v = hp[k]; s += v.x+v.y+v.z+v.w; }
    seg[tid]=s; __syncthreads();
    for (int off=1; off<1024; off<<=1){
        unsigned v = (tid+off<1024) ? seg[tid+off] : 0u;
        __syncthreads();
        seg[tid] += v;
        __syncthreads();
    }
    if (seg[tid] >= PRE && (tid==1023 || seg[tid+1] < PRE)) tstar = tid;
    __syncthreads();
    if (tid==0){
        int t = tstar;
        unsigned cum = (t < 1023) ? seg[t+1] : 0u;
        int T = t*64;
        for (int b = t*64+63; b >= t*64; b--){
            cum += g_hist[n*NBINS + b];
            if (cum >= PRE){ T = b; break; }
        }
        int thrv = (T > 0) ? (T - 1) : 0;      // one-bin safety margin
        g_thr[n] = thrv;
        // fast path valid iff static pre-gather provably supersets top-2000 bins
        bool fast = (STATIC_BIN <= thrv) && (g_cnt[n] <= CAP);
        g_need[n] = fast ? 0 : 1;
        if (!fast) g_cnt[n] = 0;               // re-gather from scratch
    }
}

__device__ __forceinline__ void ce_reg(unsigned long long &a, unsigned long long &b, bool desc){
    if (desc ? (a < b) : (a > b)){ unsigned long long t=a; a=b; b=t; }
}

// stages j = jmax..1 (jmax <= 64) on the 128-element block b, warp-local
__device__ __forceinline__ void reg_stages(unsigned long long r[4], int b, int lane,
                                           int ksz, int jmax){
    if (jmax >= 64){
        bool d0 = (((b*128 + 0*32 + lane) & ksz) == 0);
        bool d1 = (((b*128 + 1*32 + lane) & ksz) == 0);
        ce_reg(r[0], r[2], d0);
        ce_reg(r[1], r[3], d1);
    }
    if (jmax >= 32){
        bool d0 = (((b*128 + 0*32 + lane) & ksz) == 0);
        bool d2 = (((b*128 + 2*32 + lane) & ksz) == 0);
        ce_reg(r[0], r[1], d0);
        ce_reg(r[2], r[3], d2);
    }
    int js = (jmax < 16) ? jmax : 16;
    for (int j = js; j >= 1; j >>= 1){
        #pragma unroll
        for (int k = 0; k < 4; k++){
            unsigned long long partner = __shfl_xor_sync(0xFFFFFFFFu, r[k], j);
            int idx_low = b*128 + k*32 + (lane & ~j);
            bool desc = ((idx_low & ksz) == 0);
            bool lower = ((lane & j) == 0);
            bool take_max = (lower == desc);
            r[k] = take_max ? (r[k] > partner ? r[k] : partner)
                            : (r[k] < partner ? r[k] : partner);
        }
    }
}

__global__ __launch_bounds__(1024) void k_sortdecode(const float4* __restrict__ logits,
                             const float* __restrict__ regs,
                             const float* __restrict__ anchors,
                             const int*   __restrict__ sizes){
    int n = blockIdx.x;
    int tid = threadIdx.x;   // 1024 threads = 32 warps
    int lane = tid & 31;
    int b    = tid >> 5;     // warp id = 128-element block id
    __shared__ unsigned long long s[CAP];

    // fallback gather (only if static pre-gather was insufficient)
    if (g_need[n]){
        int thr = g_thr[n];
        for (int t = tid; t < AHW4; t += 1024){
            float4 v = logits[(size_t)n*AHW4 + t];
            float vv[4] = {v.x, v.y, v.z, v.w};
            #pragma unroll
            for (int k=0;k<4;k++){
                if ((int)(lkey(vv[k]) >> 16) >= thr) emit_cand(n, vv[k], t*4 + k);
            }
        }
        __syncthreads();
    }

    int cnt = g_cnt[n]; if (cnt > CAP) cnt = CAP;
    for (int k = tid; k < CAP; k += 1024)
        s[k] = (k < cnt) ? g_cand[n*CAP + k] : 0ull;
    __syncthreads();

    // Phase A: all ksz=2..128 stages, warp-local (registers + shfl)
    {
        unsigned long long r[4];
        #pragma unroll
        for (int k = 0; k < 4; k++) r[k] = s[b*128 + k*32 + lane];
        #pragma unroll
        for (int ksz = 2; ksz <= 128; ksz <<= 1)
            reg_stages(r, b, lane, ksz, ksz >> 1);
        #pragma unroll
        for (int k = 0; k < 4; k++) s[b*128 + k*32 + lane] = r[k];
    }
    __syncthreads();

    // Phase B: ksz = 256..4096; smem CE for j>=128, register phase for j<=64
    for (int ksz = 256; ksz <= CAP; ksz <<= 1){
        for (int j = ksz >> 1; j >= 128; j >>= 1){
            #pragma unroll 1
            for (int c = tid; c < CAP/2; c += 1024){
                int lo = c & (j-1);
                int idx = ((c ^ lo) << 1) | lo;
                int p = idx | j;
                unsigned long long a = s[idx], bb = s[p];
                bool desc = ((idx & ksz) == 0);
                if (desc ? (a < bb) : (a > bb)){ s[idx] = bb; s[p] = a; }
            }
            __syncthreads();
        }
        {
            unsigned long long r[4];
            #pragma unroll
            for (int k = 0; k < 4; k++) r[k] = s[b*128 + k*32 + lane];
            reg_stages(r, b, lane, ksz, 64);
            #pragma unroll
            for (int k = 0; k < 4; k++) s[b*128 + k*32 + lane] = r[k];
        }
        __syncthreads();
    }

    float fh = (float)sizes[n*2+0];
    float fw = (float)sizes[n*2+1];
    for (int r = tid; r < PRE; r += 1024){
        unsigned long long v = s[r];
        unsigned key = (unsigned)(v >> 32);
        unsigned idx = 0xFFFFFFFFu - (unsigned)(v & 0xFFFFFFFFull);
        float score = __uint_as_float(key ^ 0x80000000u);
        float4 anc = ((const float4*)anchors)[(size_t)n*AHW + idx];
        int a = (int)(idx % (unsigned)AA);
        int pix = (int)(idx / (unsigned)AA);
        const float* rb = regs + (size_t)n*(AA*4*HWP) + (size_t)a*4*HWP + pix;
        float r0 = rb[0];
        float r1 = rb[HWP];
        float r2 = rb[2*HWP];
        float r3 = rb[3*HWP];
        float ws = anc.z - anc.x + 1.0f;
        float hs = anc.w - anc.y + 1.0f;
        float xc = anc.x + 0.5f*ws;
        float yc = anc.y + 0.5f*hs;
        float dw = fminf(r2, MAXOFF);
        float dh = fminf(r3, MAXOFF);
        xc = xc + r0*ws;
        yc = yc + r1*hs;
        ws = ws * expf(dw);
        hs = hs * expf(dh);
        float x1 = xc - 0.5f*ws;
        float y1 = yc - 0.5f*hs;
        float x2 = xc + 0.5f*ws - 1.0f;
        float y2 = yc + 0.5f*hs - 1.0f;
        x1 = fminf(fmaxf(x1, 0.0f), fw - 1.0f);
        y1 = fminf(fmaxf(y1, 0.0f), fh - 1.0f);
        x2 = fminf(fmaxf(x2, 0.0f), fw - 1.0f);
        y2 = fminf(fmaxf(y2, 0.0f), fh - 1.0f);
        g_boxes[n*PRE + r] = make_float4(x1,y1,x2,y2);
        g_sc[n*PRE + r] = score;
    }
}

// Upper-triangle tile IoU mask. grid = (528, NB), 256 threads.
__global__ void k_mask(){
    int n = blockIdx.y;
    int p = blockIdx.x;
    int ti = 0;
    while (p >= 32 - ti){ p -= 32 - ti; ti++; }
    int tj = ti + p;

    __shared__ float4 rb[64];
    __shared__ float4 cb[64];
    __shared__ float  ca[64];
    int tid = threadIdx.x;
    if (tid < 64){
        int gi = ti*64 + tid;
        rb[tid] = (gi < PRE) ? g_boxes[n*PRE + gi] : make_float4(0.f,0.f,-1.f,-1.f);
    } else if (tid < 128){
        int t = tid - 64;
        int gj = tj*64 + t;
        float4 b = (gj < PRE) ? g_boxes[n*PRE + gj] : make_float4(0.f,0.f,-1.f,-1.f);
        cb[t] = b;
        ca[t] = (b.z - b.x + 1.0f) * (b.w - b.y + 1.0f);
    }
    __syncthreads();

    int rid = tid >> 3;       // 0..31
    int q   = tid & 7;
    int iA = ti*64 + rid;
    int iB = iA + 32;
    float4 bA = rb[rid];
    float4 bB = rb[rid + 32];
    float aA = (bA.z - bA.x + 1.0f) * (bA.w - bA.y + 1.0f);
    float aB = (bB.z - bB.x + 1.0f) * (bB.w - bB.y + 1.0f);

    unsigned long long wA = 0ull, wB = 0ull;
    #pragma unroll
    for (int jj = 0; jj < 8; jj++){
        int j = jj*8 + q;            // strided -> conflict-free LDS across q
        int jg = tj*64 + j;
        if (jg >= PRE) continue;
        float4 bj = cb[j];
        float aj = ca[j];
        float xtlA = fmaxf(bA.x, bj.x), ytlA = fmaxf(bA.y, bj.y);
        float xbrA = fminf(bA.z, bj.z), ybrA = fminf(bA.w, bj.w);
        float iwA = fmaxf(xbrA - xtlA + 1.0f, 0.0f);
        float ihA = fmaxf(ybrA - ytlA + 1.0f, 0.0f);
        float interA = iwA * ihA;
        float denomA = aA + aj - interA;
        if (jg > iA && interA > 0.6f * denomA)
            if (interA / denomA > THR) wA |= (1ull << j);
        float xtlB = fmaxf(bB.x, bj.x), ytlB = fmaxf(bB.y, bj.y);
        float xbrB = fminf(bB.z, bj.z), ybrB = fminf(bB.w, bj.w);
        float iwB = fmaxf(xbrB - xtlB + 1.0f, 0.0f);
        float ihB = fmaxf(ybrB - ytlB + 1.0f, 0.0f);
        float interB = iwB * ihB;
        float denomB = aB + aj - interB;
        if (jg > iB && interB > 0.6f * denomB)
            if (interB / denomB > THR) wB |= (1ull << j);
    }
    wA |= __shfl_xor_sync(0xFFFFFFFFu, wA, 1, 8);
    wA |= __shfl_xor_sync(0xFFFFFFFFu, wA, 2, 8);
    wA |= __shfl_xor_sync(0xFFFFFFFFu, wA, 4, 8);
    wB |= __shfl_xor_sync(0xFFFFFFFFu, wB, 1, 8);
    wB |= __shfl_xor_sync(0xFFFFFFFFu, wB, 2, 8);
    wB |= __shfl_xor_sync(0xFFFFFFFFu, wB, 4, 8);
    if (q == 0){
        if (iA < PRE) g_mask[((size_t)n*ROWS_PAD + iA)*MW + tj] = wA;
        if (iB < PRE) g_mask[((size_t)n*ROWS_PAD + iB)*MW + tj] = wB;
    }
}

#define TS 33
__global__ __launch_bounds__(512) void k_scan(float* __restrict__ out){
    int n = blockIdx.x;
    int tid = threadIdx.x;    // 512 = 16 warps
    int lane = tid & 31;
    int wrp  = tid >> 5;
    __shared__ unsigned long long remv[MW];
    __shared__ unsigned long long tile[2][64*TS];
    __shared__ unsigned long long sh_alive;
    __shared__ int kb[MW+1];
    if (tid < MW) remv[tid] = 0ull;

    {
        const unsigned long long* gp = &g_mask[((size_t)n*ROWS_PAD)*MW];
        #pragma unroll
        for (int q = 0; q < 4; q++){
            int k = tid + q*512;
            tile[0][(k >> 5)*TS + (k & 31)] = gp[k];
        }
    }
    __syncthreads();

    for (int blk = 0; blk < MW; blk++){
        int cur = blk & 1, nxt = cur ^ 1;
        int base = blk*64;
        int nrows = PRE - base; if (nrows > 64) nrows = 64;

        unsigned long long pf[4];
        bool has_next = (blk + 1 < MW);
        if (has_next){
            const unsigned long long* gp = &g_mask[((size_t)n*ROWS_PAD + (blk+1)*64)*MW];
            #pragma unroll
            for (int q = 0; q < 4; q++) pf[q] = gp[tid + q*512];
        }

        if (tid == 0){
            unsigned long long w0 = remv[blk];
            unsigned long long alive = 0ull;
            #pragma unroll
            for (int rr = 0; rr < 64; rr++){
                if (rr < nrows){
                    unsigned long long m = tile[cur][rr*TS + blk];
                    if (!((w0 >> rr) & 1ull)){
                        alive |= (1ull << rr);
                        w0 |= m;
                    }
                }
            }
            remv[blk] = w0;
            sh_alive = alive;
        }
        __syncthreads();

        unsigned long long alive = sh_alive;
        unsigned long long acc = 0ull;
        for (int rr = wrp; rr < nrows; rr += 16){
            if ((alive >> rr) & 1ull) acc |= tile[cur][rr*TS + lane];
        }
        if (acc && lane > blk) atomicOr(&remv[lane], acc);

        if (has_next){
            #pragma unroll
            for (int q = 0; q < 4; q++){
                int k = tid + q*512;
                tile[nxt][(k >> 5)*TS + (k & 31)] = pf[q];
            }
        }
        __syncthreads();
    }

    if (tid == 0){
        int c = 0;
        for (int ww = 0; ww < MW; ww++){
            kb[ww] = c;
            unsigned long long valid = (ww == MW-1) ? 0xFFFFull : ~0ull;
            c += __popcll((~remv[ww]) & valid);
        }
        kb[MW] = c;
    }
    __syncthreads();
    // stable partition: kept (in order) then suppressed (in order) == post top_k
    for (int i = tid; i < PRE; i += 512){
        int ww = i >> 6, b = i & 63;
        unsigned long long valid = (ww == MW-1) ? 0xFFFFull : ~0ull;
        unsigned long long notr = (~remv[ww]) & valid;
        bool keep = (notr >> b) & 1ull;
        unsigned long long below = b ? (notr & ((~0ull) >> (64 - b))) : 0ull;
        int kbelow = kb[ww] + __popcll(below);
        int pos = keep ? kbelow : (kb[MW] + (i - kbelow));
        if (pos < POST){
            float4 bx = g_boxes[n*PRE + i];
            float sc = keep ? g_sc[n*PRE + i] : -1.0f;
            float* op = out + ((size_t)n*POST + pos)*5;
            op[0]=bx.x; op[1]=bx.y; op[2]=bx.z; op[3]=bx.w; op[4]=sc;
        }
    }
}

extern "C" void kernel_launch(void* const* d_in, const int* in_sizes, int n_in,
                              void* d_out, int out_size){
    (void)in_sizes; (void)n_in; (void)out_size;
    const float* logits  = (const float*)d_in[0];
    const float* regs    = (const float*)d_in[1];
    const float* anchors = (const float*)d_in[2];
    const int*   sizes   = (const int*)d_in[3];
    float* out = (float*)d_out;

    k_zero<<<(NB*NBINS/4 + 255)/256, 256>>>();
    dim3 g((AHW4 + 255)/256, NB);
    k_hist<<<g, 256>>>((const float4*)logits);
    k_thresh<<<NB, 1024>>>();
    k_sortdecode<<<NB, 1024>>>((const float4*)logits, regs, anchors, sizes);
    k_mask<<<dim3(528, NB), 256>>>();
    k_scan<<<NB, 512>>>(out);
}

// round 7
// speedup vs baseline: 6.5538x; 1.0127x over previous
#include <cuda_runtime.h>
#include <math.h>

#define NB 8
#define AA 3
#define HH 200
#define WW 336
#define HWP (HH*WW)          // 67200
#define AHW (AA*HWP)         // 201600
#define AHW4 (AHW/4)         // 50400
#define PRE 2000
#define POST 1000
#define THR 0.7f
#define MAXOFF 4.135166556742356f
#define CAP 4096
#define NBINS 65536
#define STATIC_BIN 49164     // logit-key bin of ~2.1875 (score ~0.9)
#define MW 32
#define ROWS_PAD 2048

__device__ unsigned int        g_hist[NB*NBINS];
__device__ int                 g_cnt[NB];
__device__ unsigned long long  g_cand[NB*CAP];
__device__ float4              g_boxes[NB*PRE];
__device__ float               g_sc[NB*PRE];
// row-major: g_mask[n][row][word], only words w >= row/64 are valid
__device__ unsigned long long  g_mask[(size_t)NB*ROWS_PAD*MW];

// orderable key of raw logit (monotone with sigmoid)
__device__ __forceinline__ unsigned lkey(float x){
    unsigned b = __float_as_uint(x);
    return (b & 0x80000000u) ? ~b : (b | 0x80000000u);
}

// exact reference score key (sigmoid), computed only for candidates
__device__ __forceinline__ unsigned skey(float x){
    float s = 1.0f/(1.0f + expf(-x));
    return __float_as_uint(s) | 0x80000000u;   // s > 0 -> orderable
}

__device__ __forceinline__ void emit_cand(int n, float x, int el){
    int pos = atomicAdd(&g_cnt[n], 1);
    if (pos < CAP){
        int a = el / HWP;
        int pix = el - a*HWP;
        unsigned idx = (unsigned)(pix*AA + a);     // score-space index
        g_cand[n*CAP + pos] =
            ((unsigned long long)skey(x) << 32) | (unsigned long long)(0xFFFFFFFFu - idx);
    }
}

// hist on logit bins + opportunistic gather (bin >= STATIC_BIN)
// relies on g_hist/g_cnt being zero (static init on call 1; tails of
// k_mask/k_scan re-zero them for every subsequent call)
__global__ void k_hist(const float4* __restrict__ logits){
    int n = blockIdx.y;
    int t = blockIdx.x*blockDim.x + threadIdx.x;
    if (t >= AHW4) return;
    float4 v = logits[(size_t)n*AHW4 + t];
    float vv[4] = {v.x, v.y, v.z, v.w};
    #pragma unroll
    for (int k = 0; k < 4; k++){
        unsigned bin = lkey(vv[k]) >> 16;
        atomicAdd(&g_hist[n*NBINS + bin], 1u);
        if (bin >= STATIC_BIN) emit_cand(n, vv[k], t*4 + k);
    }
}

__device__ __forceinline__ void ce_reg(unsigned long long &a, unsigned long long &b, bool desc){
    if (desc ? (a < b) : (a > b)){ unsigned long long t=a; a=b; b=t; }
}

// stages j = jmax..1 (jmax <= 64) on the 128-element block b, warp-local
__device__ __forceinline__ void reg_stages(unsigned long long r[4], int b, int lane,
                                           int ksz, int jmax){
    if (jmax >= 64){
        bool d0 = (((b*128 + 0*32 + lane) & ksz) == 0);
        bool d1 = (((b*128 + 1*32 + lane) & ksz) == 0);
        ce_reg(r[0], r[2], d0);
        ce_reg(r[1], r[3], d1);
    }
    if (jmax >= 32){
        bool d0 = (((b*128 + 0*32 + lane) & ksz) == 0);
        bool d2 = (((b*128 + 2*32 + lane) & ksz) == 0);
        ce_reg(r[0], r[1], d0);
        ce_reg(r[2], r[3], d2);
    }
    int js = (jmax < 16) ? jmax : 16;
    for (int j = js; j >= 1; j >>= 1){
        #pragma unroll
        for (int k = 0; k < 4; k++){
            unsigned long long partner = __shfl_xor_sync(0xFFFFFFFFu, r[k], j);
            int idx_low = b*128 + k*32 + (lane & ~j);
            bool desc = ((idx_low & ksz) == 0);
            bool lower = ((lane & j) == 0);
            bool take_max = (lower == desc);
            r[k] = take_max ? (r[k] > partner ? r[k] : partner)
                            : (r[k] < partner ? r[k] : partner);
        }
    }
}

// thresh + (fallback gather) + bitonic sort + decode, one block per batch
__global__ __launch_bounds__(1024) void k_sortdecode(const float4* __restrict__ logits,
                             const float* __restrict__ regs,
                             const float* __restrict__ anchors,
                             const int*   __restrict__ sizes){
    int n = blockIdx.x;
    int tid = threadIdx.x;   // 1024 threads = 32 warps
    int lane = tid & 31;
    int b    = tid >> 5;     // warp id = 128-element block id
    __shared__ unsigned long long s[CAP];
    __shared__ int tstar, sh_thr, sh_fast, sh_cnt;

    // ---- threshold from histogram (suffix scan; seg aliases s) ----
    {
        unsigned* seg = (unsigned*)s;
        const uint4* hp = (const uint4*)(g_hist + n*NBINS + tid*64);
        unsigned acc = 0;
        #pragma unroll
        for (int k=0;k<16;k++){ uint4 v = hp[k]; acc += v.x+v.y+v.z+v.w; }
        seg[tid] = acc; __syncthreads();
        for (int off=1; off<1024; off<<=1){
            unsigned v = (tid+off<1024) ? seg[tid+off] : 0u;
            __syncthreads();
            seg[tid] += v;
            __syncthreads();
        }
        if (seg[tid] >= PRE && (tid==1023 || seg[tid+1] < PRE)) tstar = tid;
        __syncthreads();
        if (tid==0){
            int t = tstar;
            unsigned cum = (t < 1023) ? seg[t+1] : 0u;
            int T = t*64;
            for (int bb = t*64+63; bb >= t*64; bb--){
                cum += g_hist[n*NBINS + bb];
                if (cum >= PRE){ T = bb; break; }
            }
            int thrv = (T > 0) ? (T - 1) : 0;      // one-bin safety margin
            int cnt0 = atomicAdd(&g_cnt[n], 0);
            bool fast = (STATIC_BIN <= thrv) && (cnt0 <= CAP);
            sh_thr = thrv; sh_fast = fast ? 1 : 0; sh_cnt = cnt0;
            if (!fast) atomicExch(&g_cnt[n], 0);   // re-gather from scratch
        }
        __syncthreads();
    }

    // ---- fallback gather (only if static pre-gather was insufficient) ----
    if (!sh_fast){
        int thr = sh_thr;
        for (int t = tid; t < AHW4; t += 1024){
            float4 v = logits[(size_t)n*AHW4 + t];
            float vv[4] = {v.x, v.y, v.z, v.w};
            #pragma unroll
            for (int k=0;k<4;k++){
                if ((int)(lkey(vv[k]) >> 16) >= thr) emit_cand(n, vv[k], t*4 + k);
            }
        }
        __syncthreads();
        if (tid == 0) sh_cnt = atomicAdd(&g_cnt[n], 0);
        __syncthreads();
    }

    int cnt = sh_cnt; if (cnt > CAP) cnt = CAP;
    for (int k = tid; k < CAP; k += 1024)
        s[k] = (k < cnt) ? g_cand[n*CAP + k] : 0ull;
    __syncthreads();

    // Phase A: all ksz=2..128 stages, warp-local (registers + shfl)
    {
        unsigned long long r[4];
        #pragma unroll
        for (int k = 0; k < 4; k++) r[k] = s[b*128 + k*32 + lane];
        #pragma unroll
        for (int ksz = 2; ksz <= 128; ksz <<= 1)
            reg_stages(r, b, lane, ksz, ksz >> 1);
        #pragma unroll
        for (int k = 0; k < 4; k++) s[b*128 + k*32 + lane] = r[k];
    }
    __syncthreads();

    // Phase B: ksz = 256..4096; paired smem stages for j>=128, reg phase j<=64
    for (int ksz = 256; ksz <= CAP; ksz <<= 1){
        int j = ksz >> 1;
        while (j >= 256){
            int j1 = j, j2 = j >> 1;
            int s2 = __ffs(j2) - 1;
            int c = tid;                                  // 1024 groups of 4
            int idx = ((c >> s2) << (s2+2)) | (c & (j2-1));
            unsigned long long e0 = s[idx];
            unsigned long long e1 = s[idx + j2];
            unsigned long long e2 = s[idx + j1];
            unsigned long long e3 = s[idx + j1 + j2];
            bool desc = ((idx & ksz) == 0);
            ce_reg(e0, e2, desc); ce_reg(e1, e3, desc);   // stage j1
            ce_reg(e0, e1, desc); ce_reg(e2, e3, desc);   // stage j2
            s[idx] = e0; s[idx + j2] = e1; s[idx + j1] = e2; s[idx + j1 + j2] = e3;
            __syncthreads();
            j >>= 2;
        }
        if (j == 128){
            #pragma unroll
            for (int t = 0; t < 2; t++){
                int c = tid + t*1024;
                int idx = ((c >> 7) << 8) | (c & 127);
                int p = idx | 128;
                unsigned long long a = s[idx], bb2 = s[p];
                bool desc = ((idx & ksz) == 0);
                if (desc ? (a < bb2) : (a > bb2)){ s[idx] = bb2; s[p] = a; }
            }
            __syncthreads();
        }
        {
            unsigned long long r[4];
            #pragma unroll
            for (int k = 0; k < 4; k++) r[k] = s[b*128 + k*32 + lane];
            reg_stages(r, b, lane, ksz, 64);
            #pragma unroll
            for (int k = 0; k < 4; k++) s[b*128 + k*32 + lane] = r[k];
        }
        __syncthreads();
    }

    float fh = (float)sizes[n*2+0];
    float fw = (float)sizes[n*2+1];
    for (int r = tid; r < PRE; r += 1024){
        unsigned long long v = s[r];
        unsigned key = (unsigned)(v >> 32);
        unsigned idx = 0xFFFFFFFFu - (unsigned)(v & 0xFFFFFFFFull);
        float score = __uint_as_float(key ^ 0x80000000u);
        float4 anc = ((const float4*)anchors)[(size_t)n*AHW + idx];
        int a = (int)(idx % (unsigned)AA);
        int pix = (int)(idx / (unsigned)AA);
        const float* rb = regs + (size_t)n*(AA*4*HWP) + (size_t)a*4*HWP + pix;
        float r0 = rb[0];
        float r1 = rb[HWP];
        float r2 = rb[2*HWP];
        float r3 = rb[3*HWP];
        float ws = anc.z - anc.x + 1.0f;
        float hs = anc.w - anc.y + 1.0f;
        float xc = anc.x + 0.5f*ws;
        float yc = anc.y + 0.5f*hs;
        float dw = fminf(r2, MAXOFF);
        float dh = fminf(r3, MAXOFF);
        xc = xc + r0*ws;
        yc = yc + r1*hs;
        ws = ws * expf(dw);
        hs = hs * expf(dh);
        float x1 = xc - 0.5f*ws;
        float y1 = yc - 0.5f*hs;
        float x2 = xc + 0.5f*ws - 1.0f;
        float y2 = yc + 0.5f*hs - 1.0f;
        x1 = fminf(fmaxf(x1, 0.0f), fw - 1.0f);
        y1 = fminf(fmaxf(y1, 0.0f), fh - 1.0f);
        x2 = fminf(fmaxf(x2, 0.0f), fw - 1.0f);
        y2 = fminf(fmaxf(y2, 0.0f), fh - 1.0f);
        g_boxes[n*PRE + r] = make_float4(x1,y1,x2,y2);
        g_sc[n*PRE + r] = score;
    }
}

// Upper-triangle tile IoU mask. grid = (528, NB), 256 threads.
// Tail: re-zero g_hist for the next call.
__global__ void k_mask(){
    int n = blockIdx.y;
    int p = blockIdx.x;
    int ti = 0;
    while (p >= 32 - ti){ p -= 32 - ti; ti++; }
    int tj = ti + p;

    __shared__ float4 rb[64];
    __shared__ float4 cb[64];
    __shared__ float  ca[64];
    int tid = threadIdx.x;
    if (tid < 64){
        int gi = ti*64 + tid;
        rb[tid] = (gi < PRE) ? g_boxes[n*PRE + gi] : make_float4(0.f,0.f,-1.f,-1.f);
    } else if (tid < 128){
        int t = tid - 64;
        int gj = tj*64 + t;
        float4 b = (gj < PRE) ? g_boxes[n*PRE + gj] : make_float4(0.f,0.f,-1.f,-1.f);
        cb[t] = b;
        ca[t] = (b.z - b.x + 1.0f) * (b.w - b.y + 1.0f);
    }
    __syncthreads();

    int rid = tid >> 3;       // 0..31
    int q   = tid & 7;
    int iA = ti*64 + rid;
    int iB = iA + 32;
    float4 bA = rb[rid];
    float4 bB = rb[rid + 32];
    float aA = (bA.z - bA.x + 1.0f) * (bA.w - bA.y + 1.0f);
    float aB = (bB.z - bB.x + 1.0f) * (bB.w - bB.y + 1.0f);

    unsigned long long wA = 0ull, wB = 0ull;
    #pragma unroll
    for (int jj = 0; jj < 8; jj++){
        int j = jj*8 + q;            // strided -> conflict-free LDS across q
        int jg = tj*64 + j;
        if (jg >= PRE) continue;
        float4 bj = cb[j];
        float aj = ca[j];
        float xtlA = fmaxf(bA.x, bj.x), ytlA = fmaxf(bA.y, bj.y);
        float xbrA = fminf(bA.z, bj.z), ybrA = fminf(bA.w, bj.w);
        float iwA = fmaxf(xbrA - xtlA + 1.0f, 0.0f);
        float ihA = fmaxf(ybrA - ytlA + 1.0f, 0.0f);
        float interA = iwA * ihA;
        float denomA = aA + aj - interA;
        if (jg > iA && interA > 0.6f * denomA)
            if (interA / denomA > THR) wA |= (1ull << j);
        float xtlB = fmaxf(bB.x, bj.x), ytlB = fmaxf(bB.y, bj.y);
        float xbrB = fminf(bB.z, bj.z), ybrB = fminf(bB.w, bj.w);
        float iwB = fmaxf(xbrB - xtlB + 1.0f, 0.0f);
        float ihB = fmaxf(ybrB - ytlB + 1.0f, 0.0f);
        float interB = iwB * ihB;
        float denomB = aB + aj - interB;
        if (jg > iB && interB > 0.6f * denomB)
            if (interB / denomB > THR) wB |= (1ull << j);
    }
    wA |= __shfl_xor_sync(0xFFFFFFFFu, wA, 1, 8);
    wA |= __shfl_xor_sync(0xFFFFFFFFu, wA, 2, 8);
    wA |= __shfl_xor_sync(0xFFFFFFFFu, wA, 4, 8);
    wB |= __shfl_xor_sync(0xFFFFFFFFu, wB, 1, 8);
    wB |= __shfl_xor_sync(0xFFFFFFFFu, wB, 2, 8);
    wB |= __shfl_xor_sync(0xFFFFFFFFu, wB, 4, 8);
    if (q == 0){
        if (iA < PRE) g_mask[((size_t)n*ROWS_PAD + iA)*MW + tj] = wA;
        if (iB < PRE) g_mask[((size_t)n*ROWS_PAD + iB)*MW + tj] = wB;
    }

    // tail: zero g_hist for the next call (independent of this kernel's data)
    unsigned gid = (blockIdx.y*gridDim.x + blockIdx.x)*blockDim.x + threadIdx.x;
    if (gid < (unsigned)(NB*NBINS/4))
        ((uint4*)g_hist)[gid] = make_uint4(0,0,0,0);
}

#define TS 33
__global__ __launch_bounds__(512) void k_scan(float* __restrict__ out){
    int n = blockIdx.x;
    int tid = threadIdx.x;    // 512 = 16 warps
    int lane = tid & 31;
    int wrp  = tid >> 5;
    __shared__ unsigned long long remv[MW];
    __shared__ unsigned long long tile[2][64*TS];
    __shared__ unsigned long long sh_alive;
    __shared__ int kb[MW+1];
    if (tid < MW) remv[tid] = 0ull;

    {
        const unsigned long long* gp = &g_mask[((size_t)n*ROWS_PAD)*MW];
        #pragma unroll
        for (int q = 0; q < 4; q++){
            int k = tid + q*512;
            tile[0][(k >> 5)*TS + (k & 31)] = gp[k];
        }
    }
    __syncthreads();

    for (int blk = 0; blk < MW; blk++){
        int cur = blk & 1, nxt = cur ^ 1;
        int base = blk*64;
        int nrows = PRE - base; if (nrows > 64) nrows = 64;

        unsigned long long pf[4];
        bool has_next = (blk + 1 < MW);
        if (has_next){
            const unsigned long long* gp = &g_mask[((size_t)n*ROWS_PAD + (blk+1)*64)*MW];
            #pragma unroll
            for (int q = 0; q < 4; q++) pf[q] = gp[tid + q*512];
        }

        if (tid == 0){
            unsigned long long w0 = remv[blk];
            unsigned long long alive = 0ull;
            #pragma unroll
            for (int rr = 0; rr < 64; rr++){
                if (rr < nrows){
                    unsigned long long m = tile[cur][rr*TS + blk];
                    if (!((w0 >> rr) & 1ull)){
                        alive |= (1ull << rr);
                        w0 |= m;
                    }
                }
            }
            remv[blk] = w0;
            sh_alive = alive;
        }
        __syncthreads();

        unsigned long long alive = sh_alive;
        unsigned long long acc = 0ull;
        for (int rr = wrp; rr < nrows; rr += 16){
            if ((alive >> rr) & 1ull) acc |= tile[cur][rr*TS + lane];
        }
        if (acc && lane > blk) atomicOr(&remv[lane], acc);

        if (has_next){
            #pragma unroll
            for (int q = 0; q < 4; q++){
                int k = tid + q*512;
                tile[nxt][(k >> 5)*TS + (k & 31)] = pf[q];
            }
        }
        __syncthreads();
    }

    if (tid == 0){
        int c = 0;
        for (int ww = 0; ww < MW; ww++){
            kb[ww] = c;
            unsigned long long valid = (ww == MW-1) ? 0xFFFFull : ~0ull;
            c += __popcll((~remv[ww]) & valid);
        }
        kb[MW] = c;
        g_cnt[n] = 0;           // tail: reset candidate counter for next call
    }
    __syncthreads();
    // stable partition: kept (in order) then suppressed (in order) == post top_k
    for (int i = tid; i < PRE; i += 512){
        int ww = i >> 6, b = i & 63;
        unsigned long long valid = (ww == MW-1) ? 0xFFFFull : ~0ull;
        unsigned long long notr = (~remv[ww]) & valid;
        bool keep = (notr >> b) & 1ull;
        unsigned long long below = b ? (notr & ((~0ull) >> (64 - b))) : 0ull;
        int kbelow = kb[ww] + __popcll(below);
        int pos = keep ? kbelow : (kb[MW] + (i - kbelow));
        if (pos < POST){
            float4 bx = g_boxes[n*PRE + i];
            float sc = keep ? g_sc[n*PRE + i] : -1.0f;
            float* op = out + ((size_t)n*POST + pos)*5;
            op[0]=bx.x; op[1]=bx.y; op[2]=bx.z; op[3]=bx.w; op[4]=sc;
        }
    }
}

extern "C" void kernel_launch(void* const* d_in, const int* in_sizes, int n_in,
                              void* d_out, int out_size){
    (void)in_sizes; (void)n_in; (void)out_size;
    const float* logits  = (const float*)d_in[0];
    const float* regs    = (const float*)d_in[1];
    const float* anchors = (const float*)d_in[2];
    const int*   sizes   = (const int*)d_in[3];
    float* out = (float*)d_out;

    dim3 g((AHW4 + 255)/256, NB);
    k_hist<<<g, 256>>>((const float4*)logits);
    k_sortdecode<<<NB, 1024>>>((const float4*)logits, regs, anchors, sizes);
    k_mask<<<dim3(528, NB), 256>>>();
    k_scan<<<NB, 512>>>(out);
}

// round 8
// speedup vs baseline: 7.4617x; 1.1385x over previous
#include <cuda_runtime.h>
#include <math.h>

#define NB 8
#define AA 3
#define HH 200
#define WW 336
#define HWP (HH*WW)          // 67200
#define AHW (AA*HWP)         // 201600
#define AHW4 (AHW/4)         // 50400
#define PRE 2000
#define POST 1000
#define THR 0.7f
#define MAXOFF 4.135166556742356f
#define CAP 4096
#define NBINS 65536
#define STATIC_BIN 49164     // logit-key bin of ~2.1875 (score ~0.9)
#define MW 32
#define ROWS_PAD 2048

__device__ unsigned int        g_hist[NB*NBINS];
__device__ int                 g_cnt[NB];
__device__ unsigned long long  g_cand[NB*CAP];
__device__ float4              g_boxes[NB*PRE];
__device__ float               g_sc[NB*PRE];
// row-major: g_mask[n][row][word], only words w >= row/64 are valid
__device__ unsigned long long  g_mask[(size_t)NB*ROWS_PAD*MW];

// orderable key of raw logit (monotone with sigmoid)
__device__ __forceinline__ unsigned lkey(float x){
    unsigned b = __float_as_uint(x);
    return (b & 0x80000000u) ? ~b : (b | 0x80000000u);
}

// exact reference score key (sigmoid), computed only for candidates
__device__ __forceinline__ unsigned skey(float x){
    float s = 1.0f/(1.0f + expf(-x));
    return __float_as_uint(s) | 0x80000000u;   // s > 0 -> orderable
}

__device__ __forceinline__ void emit_cand(int n, float x, int el){
    int pos = atomicAdd(&g_cnt[n], 1);
    if (pos < CAP){
        int a = el / HWP;
        int pix = el - a*HWP;
        unsigned idx = (unsigned)(pix*AA + a);     // score-space index
        g_cand[n*CAP + pos] =
            ((unsigned long long)skey(x) << 32) | (unsigned long long)(0xFFFFFFFFu - idx);
    }
}

// hist on logit bins + opportunistic gather (bin >= STATIC_BIN)
// relies on g_hist/g_cnt being zero (static init on call 1; tails of
// k_mask/k_scan re-zero them for every subsequent call)
__global__ void k_hist(const float4* __restrict__ logits){
    int n = blockIdx.y;
    int t = blockIdx.x*blockDim.x + threadIdx.x;
    if (t >= AHW4) return;
    float4 v = logits[(size_t)n*AHW4 + t];
    float vv[4] = {v.x, v.y, v.z, v.w};
    #pragma unroll
    for (int k = 0; k < 4; k++){
        unsigned bin = lkey(vv[k]) >> 16;
        atomicAdd(&g_hist[n*NBINS + bin], 1u);
        if (bin >= STATIC_BIN) emit_cand(n, vv[k], t*4 + k);
    }
}

__device__ __forceinline__ void ce_reg(unsigned long long &a, unsigned long long &b, bool desc){
    if (desc ? (a < b) : (a > b)){ unsigned long long t=a; a=b; b=t; }
}

// stages j = jmax..1 (jmax <= 64) on the 128-element block b, warp-local
__device__ __forceinline__ void reg_stages(unsigned long long r[4], int b, int lane,
                                           int ksz, int jmax){
    if (jmax >= 64){
        bool d0 = (((b*128 + 0*32 + lane) & ksz) == 0);
        bool d1 = (((b*128 + 1*32 + lane) & ksz) == 0);
        ce_reg(r[0], r[2], d0);
        ce_reg(r[1], r[3], d1);
    }
    if (jmax >= 32){
        bool d0 = (((b*128 + 0*32 + lane) & ksz) == 0);
        bool d2 = (((b*128 + 2*32 + lane) & ksz) == 0);
        ce_reg(r[0], r[1], d0);
        ce_reg(r[2], r[3], d2);
    }
    int js = (jmax < 16) ? jmax : 16;
    for (int j = js; j >= 1; j >>= 1){
        #pragma unroll
        for (int k = 0; k < 4; k++){
            unsigned long long partner = __shfl_xor_sync(0xFFFFFFFFu, r[k], j);
            int idx_low = b*128 + k*32 + (lane & ~j);
            bool desc = ((idx_low & ksz) == 0);
            bool lower = ((lane & j) == 0);
            bool take_max = (lower == desc);
            r[k] = take_max ? (r[k] > partner ? r[k] : partner)
                            : (r[k] < partner ? r[k] : partner);
        }
    }
}

// thresh + (fallback gather) + bitonic sort + decode, one block per batch
__global__ __launch_bounds__(1024) void k_sortdecode(const float4* __restrict__ logits,
                             const float* __restrict__ regs,
                             const float* __restrict__ anchors,
                             const int*   __restrict__ sizes){
    int n = blockIdx.x;
    int tid = threadIdx.x;   // 1024 threads = 32 warps
    int lane = tid & 31;
    int b    = tid >> 5;     // warp id = 128-element block id
    __shared__ unsigned long long s[CAP];
    __shared__ unsigned wsuf[32];
    __shared__ int tstar, sh_thr, sh_fast, sh_cnt;

    // ---- threshold from histogram (warp-shuffle suffix scan; seg aliases s) ----
    {
        unsigned* seg = (unsigned*)s;
        const uint4* hp = (const uint4*)(g_hist + n*NBINS + tid*64);
        unsigned acc = 0;
        #pragma unroll
        for (int k=0;k<16;k++){ uint4 v = hp[k]; acc += v.x+v.y+v.z+v.w; }
        // suffix scan within warp (suf includes own)
        unsigned a = acc;
        #pragma unroll
        for (int off=1; off<32; off<<=1){
            unsigned v = __shfl_down_sync(0xFFFFFFFFu, a, off);
            if (lane < 32-off) a += v;
        }
        if (lane == 0) wsuf[b] = a;   // warp total
        __syncthreads();
        if (tid < 32){
            unsigned w = wsuf[tid];
            #pragma unroll
            for (int off=1; off<32; off<<=1){
                unsigned v = __shfl_down_sync(0xFFFFFFFFu, w, off);
                if (tid < 32-off) w += v;
            }
            wsuf[tid] = w;            // suffix over warps incl. own
        }
        __syncthreads();
        unsigned suf = a + ((b < 31) ? wsuf[b+1] : 0u);
        seg[tid] = suf;
        __syncthreads();
        if (suf >= PRE && (tid==1023 || seg[tid+1] < PRE)) tstar = tid;
        __syncthreads();
        if (tid==0){
            int t = tstar;
            unsigned cum = (t < 1023) ? seg[t+1] : 0u;
            int T = t*64;
            for (int bb = t*64+63; bb >= t*64; bb--){
                cum += g_hist[n*NBINS + bb];
                if (cum >= PRE){ T = bb; break; }
            }
            int thrv = (T > 0) ? (T - 1) : 0;      // one-bin safety margin
            int cnt0 = atomicAdd(&g_cnt[n], 0);
            bool fast = (STATIC_BIN <= thrv) && (cnt0 <= CAP);
            sh_thr = thrv; sh_fast = fast ? 1 : 0; sh_cnt = cnt0;
            if (!fast) atomicExch(&g_cnt[n], 0);   // re-gather from scratch
        }
        __syncthreads();
    }

    // ---- fallback gather (only if static pre-gather was insufficient) ----
    if (!sh_fast){
        int thr = sh_thr;
        for (int t = tid; t < AHW4; t += 1024){
            float4 v = logits[(size_t)n*AHW4 + t];
            float vv[4] = {v.x, v.y, v.z, v.w};
            #pragma unroll
            for (int k=0;k<4;k++){
                if ((int)(lkey(vv[k]) >> 16) >= thr) emit_cand(n, vv[k], t*4 + k);
            }
        }
        __syncthreads();
        if (tid == 0) sh_cnt = atomicAdd(&g_cnt[n], 0);
        __syncthreads();
    }

    int cnt = sh_cnt; if (cnt > CAP) cnt = CAP;
    for (int k = tid; k < CAP; k += 1024)
        s[k] = (k < cnt) ? g_cand[n*CAP + k] : 0ull;
    __syncthreads();

    // Phase A: all ksz=2..128 stages, warp-local (registers + shfl)
    {
        unsigned long long r[4];
        #pragma unroll
        for (int k = 0; k < 4; k++) r[k] = s[b*128 + k*32 + lane];
        #pragma unroll
        for (int ksz = 2; ksz <= 128; ksz <<= 1)
            reg_stages(r, b, lane, ksz, ksz >> 1);
        #pragma unroll
        for (int k = 0; k < 4; k++) s[b*128 + k*32 + lane] = r[k];
    }
    __syncthreads();

    // Phase B: ksz = 256..4096; paired smem stages for j>=128, reg phase j<=64
    for (int ksz = 256; ksz <= CAP; ksz <<= 1){
        int j = ksz >> 1;
        while (j >= 256){
            int j1 = j, j2 = j >> 1;
            int s2 = __ffs(j2) - 1;
            int c = tid;                                  // 1024 groups of 4
            int idx = ((c >> s2) << (s2+2)) | (c & (j2-1));
            unsigned long long e0 = s[idx];
            unsigned long long e1 = s[idx + j2];
            unsigned long long e2 = s[idx + j1];
            unsigned long long e3 = s[idx + j1 + j2];
            bool desc = ((idx & ksz) == 0);
            ce_reg(e0, e2, desc); ce_reg(e1, e3, desc);   // stage j1
            ce_reg(e0, e1, desc); ce_reg(e2, e3, desc);   // stage j2
            s[idx] = e0; s[idx + j2] = e1; s[idx + j1] = e2; s[idx + j1 + j2] = e3;
            __syncthreads();
            j >>= 2;
        }
        if (j == 128){
            #pragma unroll
            for (int t = 0; t < 2; t++){
                int c = tid + t*1024;
                int idx = ((c >> 7) << 8) | (c & 127);
                int p = idx | 128;
                unsigned long long a = s[idx], bb2 = s[p];
                bool desc = ((idx & ksz) == 0);
                if (desc ? (a < bb2) : (a > bb2)){ s[idx] = bb2; s[p] = a; }
            }
            __syncthreads();
        }
        {
            unsigned long long r[4];
            #pragma unroll
            for (int k = 0; k < 4; k++) r[k] = s[b*128 + k*32 + lane];
            reg_stages(r, b, lane, ksz, 64);
            #pragma unroll
            for (int k = 0; k < 4; k++) s[b*128 + k*32 + lane] = r[k];
        }
        __syncthreads();
    }

    float fh = (float)sizes[n*2+0];
    float fw = (float)sizes[n*2+1];
    for (int r = tid; r < PRE; r += 1024){
        unsigned long long v = s[r];
        unsigned key = (unsigned)(v >> 32);
        unsigned idx = 0xFFFFFFFFu - (unsigned)(v & 0xFFFFFFFFull);
        float score = __uint_as_float(key ^ 0x80000000u);
        float4 anc = ((const float4*)anchors)[(size_t)n*AHW + idx];
        int a = (int)(idx % (unsigned)AA);
        int pix = (int)(idx / (unsigned)AA);
        const float* rb = regs + (size_t)n*(AA*4*HWP) + (size_t)a*4*HWP + pix;
        float r0 = rb[0];
        float r1 = rb[HWP];
        float r2 = rb[2*HWP];
        float r3 = rb[3*HWP];
        float ws = anc.z - anc.x + 1.0f;
        float hs = anc.w - anc.y + 1.0f;
        float xc = anc.x + 0.5f*ws;
        float yc = anc.y + 0.5f*hs;
        float dw = fminf(r2, MAXOFF);
        float dh = fminf(r3, MAXOFF);
        xc = xc + r0*ws;
        yc = yc + r1*hs;
        ws = ws * expf(dw);
        hs = hs * expf(dh);
        float x1 = xc - 0.5f*ws;
        float y1 = yc - 0.5f*hs;
        float x2 = xc + 0.5f*ws - 1.0f;
        float y2 = yc + 0.5f*hs - 1.0f;
        x1 = fminf(fmaxf(x1, 0.0f), fw - 1.0f);
        y1 = fminf(fmaxf(y1, 0.0f), fh - 1.0f);
        x2 = fminf(fmaxf(x2, 0.0f), fw - 1.0f);
        y2 = fminf(fmaxf(y2, 0.0f), fh - 1.0f);
        g_boxes[n*PRE + r] = make_float4(x1,y1,x2,y2);
        g_sc[n*PRE + r] = score;
    }
}

// Upper-triangle tile IoU mask. grid = (528, NB), 256 threads.
// Tail: re-zero g_hist for the next call.
__global__ void k_mask(){
    int n = blockIdx.y;
    int p = blockIdx.x;
    int ti = 0;
    while (p >= 32 - ti){ p -= 32 - ti; ti++; }
    int tj = ti + p;

    __shared__ float4 rb[64];
    __shared__ float4 cb[64];
    __shared__ float  ca[64];
    int tid = threadIdx.x;
    if (tid < 64){
        int gi = ti*64 + tid;
        rb[tid] = (gi < PRE) ? g_boxes[n*PRE + gi] : make_float4(0.f,0.f,-1.f,-1.f);
    } else if (tid < 128){
        int t = tid - 64;
        int gj = tj*64 + t;
        float4 b = (gj < PRE) ? g_boxes[n*PRE + gj] : make_float4(0.f,0.f,-1.f,-1.f);
        cb[t] = b;
        ca[t] = (b.z - b.x + 1.0f) * (b.w - b.y + 1.0f);
    }
    __syncthreads();

    int rid = tid >> 3;       // 0..31
    int q   = tid & 7;
    int iA = ti*64 + rid;
    int iB = iA + 32;
    float4 bA = rb[rid];
    float4 bB = rb[rid + 32];
    float aA = (bA.z - bA.x + 1.0f) * (bA.w - bA.y + 1.0f);
    float aB = (bB.z - bB.x + 1.0f) * (bB.w - bB.y + 1.0f);

    unsigned long long wA = 0ull, wB = 0ull;
    #pragma unroll
    for (int jj = 0; jj < 8; jj++){
        int j = jj*8 + q;            // strided -> conflict-free LDS across q
        int jg = tj*64 + j;
        if (jg >= PRE) continue;
        float4 bj = cb[j];
        float aj = ca[j];
        float xtlA = fmaxf(bA.x, bj.x), ytlA = fmaxf(bA.y, bj.y);
        float xbrA = fminf(bA.z, bj.z), ybrA = fminf(bA.w, bj.w);
        float iwA = fmaxf(xbrA - xtlA + 1.0f, 0.0f);
        float ihA = fmaxf(ybrA - ytlA + 1.0f, 0.0f);
        float interA = iwA * ihA;
        float denomA = aA + aj - interA;
        if (jg > iA && interA > 0.6f * denomA)
            if (interA / denomA > THR) wA |= (1ull << j);
        float xtlB = fmaxf(bB.x, bj.x), ytlB = fmaxf(bB.y, bj.y);
        float xbrB = fminf(bB.z, bj.z), ybrB = fminf(bB.w, bj.w);
        float iwB = fmaxf(xbrB - xtlB + 1.0f, 0.0f);
        float ihB = fmaxf(ybrB - ytlB + 1.0f, 0.0f);
        float interB = iwB * ihB;
        float denomB = aB + aj - interB;
        if (jg > iB && interB > 0.6f * denomB)
            if (interB / denomB > THR) wB |= (1ull << j);
    }
    wA |= __shfl_xor_sync(0xFFFFFFFFu, wA, 1, 8);
    wA |= __shfl_xor_sync(0xFFFFFFFFu, wA, 2, 8);
    wA |= __shfl_xor_sync(0xFFFFFFFFu, wA, 4, 8);
    wB |= __shfl_xor_sync(0xFFFFFFFFu, wB, 1, 8);
    wB |= __shfl_xor_sync(0xFFFFFFFFu, wB, 2, 8);
    wB |= __shfl_xor_sync(0xFFFFFFFFu, wB, 4, 8);
    if (q == 0){
        if (iA < PRE) g_mask[((size_t)n*ROWS_PAD + iA)*MW + tj] = wA;
        if (iB < PRE) g_mask[((size_t)n*ROWS_PAD + iB)*MW + tj] = wB;
    }

    // tail: zero g_hist for the next call (independent of this kernel's data)
    unsigned gid = (blockIdx.y*gridDim.x + blockIdx.x)*blockDim.x + threadIdx.x;
    if (gid < (unsigned)(NB*NBINS/4))
        ((uint4*)g_hist)[gid] = make_uint4(0,0,0,0);
}

#define TS 33
__global__ __launch_bounds__(512) void k_scan(float* __restrict__ out){
    int n = blockIdx.x;
    int tid = threadIdx.x;    // 512 = 16 warps
    int lane = tid & 31;
    int wrp  = tid >> 5;
    __shared__ unsigned long long remv[MW];
    __shared__ unsigned long long tile[2][64*TS];
    __shared__ unsigned long long stage[16][33];
    __shared__ unsigned long long sh_alive;
    __shared__ int kb[MW+1];
    if (tid < MW) remv[tid] = 0ull;

    {
        const unsigned long long* gp = &g_mask[((size_t)n*ROWS_PAD)*MW];
        #pragma unroll
        for (int q = 0; q < 4; q++){
            int k = tid + q*512;
            tile[0][(k >> 5)*TS + (k & 31)] = gp[k];
        }
    }
    __syncthreads();

    for (int blk = 0; blk < MW; blk++){
        int cur = blk & 1, nxt = cur ^ 1;
        int base = blk*64;
        int nrows = PRE - base; if (nrows > 64) nrows = 64;

        // issue prefetch of next tile (in flight during the chain)
        unsigned long long pf[4];
        bool has_next = (blk + 1 < MW);
        if (has_next){
            const unsigned long long* gp = &g_mask[((size_t)n*ROWS_PAD + (blk+1)*64)*MW];
            #pragma unroll
            for (int q = 0; q < 4; q++) pf[q] = gp[tid + q*512];
        }

        // serial chain, software-pipelined in 8-row register chunks
        if (tid == 0){
            unsigned long long w0 = remv[blk];
            unsigned long long alive = 0ull;
            const unsigned long long* tp = &tile[cur][blk];
            unsigned long long bufA[8], bufB[8];
            #pragma unroll
            for (int k = 0; k < 8; k++) bufA[k] = tp[k*TS];
            #pragma unroll
            for (int c = 0; c < 8; c++){
                // prefetch next chunk into the other buffer
                if (c < 7){
                    #pragma unroll
                    for (int k = 0; k < 8; k++){
                        if (c & 1) bufA[k] = tp[((c+1)*8 + k)*TS];
                        else       bufB[k] = tp[((c+1)*8 + k)*TS];
                    }
                }
                #pragma unroll
                for (int k = 0; k < 8; k++){
                    int rr = c*8 + k;
                    unsigned long long m = (c & 1) ? bufB[k] : bufA[k];
                    if (rr < nrows && !((w0 >> rr) & 1ull)){
                        alive |= (1ull << rr);
                        w0 |= m;
                    }
                }
            }
            remv[blk] = w0;
            sh_alive = alive;
        }
        __syncthreads();

        // OR phase: warp wrp covers rows wrp, wrp+16, wrp+32, wrp+48
        unsigned long long alive = sh_alive;
        unsigned long long acc = 0ull;
        for (int rr = wrp; rr < nrows; rr += 16){
            if ((alive >> rr) & 1ull) acc |= tile[cur][rr*TS + lane];
        }
        stage[wrp][lane] = acc;
        __syncthreads();

        // warp 0 combines; warps 1..15 store the prefetched tile meanwhile
        if (wrp == 0){
            unsigned long long a = 0ull;
            #pragma unroll
            for (int k = 0; k < 16; k++) a |= stage[k][lane];
            if (lane > blk) remv[lane] |= a;
        }
        if (has_next){
            #pragma unroll
            for (int q = 0; q < 4; q++){
                int k = tid + q*512;
                tile[nxt][(k >> 5)*TS + (k & 31)] = pf[q];
            }
        }
        __syncthreads();
    }

    if (tid == 0){
        int c = 0;
        for (int ww = 0; ww < MW; ww++){
            kb[ww] = c;
            unsigned long long valid = (ww == MW-1) ? 0xFFFFull : ~0ull;
            c += __popcll((~remv[ww]) & valid);
        }
        kb[MW] = c;
        g_cnt[n] = 0;           // tail: reset candidate counter for next call
    }
    __syncthreads();
    // stable partition: kept (in order) then suppressed (in order) == post top_k
    for (int i = tid; i < PRE; i += 512){
        int ww = i >> 6, b = i & 63;
        unsigned long long valid = (ww == MW-1) ? 0xFFFFull : ~0ull;
        unsigned long long notr = (~remv[ww]) & valid;
        bool keep = (notr >> b) & 1ull;
        unsigned long long below = b ? (notr & ((~0ull) >> (64 - b))) : 0ull;
        int kbelow = kb[ww] + __popcll(below);
        int pos = keep ? kbelow : (kb[MW] + (i - kbelow));
        if (pos < POST){
            float4 bx = g_boxes[n*PRE + i];
            float sc = keep ? g_sc[n*PRE + i] : -1.0f;
            float* op = out + ((size_t)n*POST + pos)*5;
            op[0]=bx.x; op[1]=bx.y; op[2]=bx.z; op[3]=bx.w; op[4]=sc;
        }
    }
}

extern "C" void kernel_launch(void* const* d_in, const int* in_sizes, int n_in,
                              void* d_out, int out_size){
    (void)in_sizes; (void)n_in; (void)out_size;
    const float* logits  = (const float*)d_in[0];
    const float* regs    = (const float*)d_in[1];
    const float* anchors = (const float*)d_in[2];
    const int*   sizes   = (const int*)d_in[3];
    float* out = (float*)d_out;

    dim3 g((AHW4 + 255)/256, NB);
    k_hist<<<g, 256>>>((const float4*)logits);
    k_sortdecode<<<NB, 1024>>>((const float4*)logits, regs, anchors, sizes);
    k_mask<<<dim3(528, NB), 256>>>();
    k_scan<<<NB, 512>>>(out);
}

// round 9
// speedup vs baseline: 11.7443x; 1.5739x over previous
#include <cuda_runtime.h>
#include <math.h>

#define NB 8
#define AA 3
#define HH 200
#define WW 336
#define HWP (HH*WW)          // 67200
#define AHW (AA*HWP)         // 201600
#define AHW4 (AHW/4)         // 50400
#define PRE 2000
#define POST 1000
#define THR 0.7f
#define MAXOFF 4.135166556742356f
#define CAP 4096
#define NBINS 65536
#define STATIC_BIN 49164     // logit-key bin of ~2.1875 (score ~0.9)
#define LOWBIN 49088         // logit-key bin of 1.5 -- bins below are not histogrammed
#define MW 32
#define ROWS_PAD 2048

__device__ unsigned int        g_hist[NB*NBINS];
__device__ int                 g_cnt[NB];
__device__ unsigned long long  g_cand[NB*CAP];
__device__ float4              g_boxes[NB*PRE];
__device__ float               g_sc[NB*PRE];
// row-major: g_mask[n][row][word], only words w >= row/64 are valid
__device__ unsigned long long  g_mask[(size_t)NB*ROWS_PAD*MW];

// orderable key of raw logit (monotone with sigmoid)
__device__ __forceinline__ unsigned lkey(float x){
    unsigned b = __float_as_uint(x);
    return (b & 0x80000000u) ? ~b : (b | 0x80000000u);
}

// exact reference score key (sigmoid), computed only for candidates
__device__ __forceinline__ unsigned skey(float x){
    float s = 1.0f/(1.0f + expf(-x));
    return __float_as_uint(s) | 0x80000000u;   // s > 0 -> orderable
}

__device__ __forceinline__ void emit_cand(int n, float x, int el){
    int pos = atomicAdd(&g_cnt[n], 1);
    if (pos < CAP){
        int a = el / HWP;
        int pix = el - a*HWP;
        unsigned idx = (unsigned)(pix*AA + a);     // score-space index
        g_cand[n*CAP + pos] =
            ((unsigned long long)skey(x) << 32) | (unsigned long long)(0xFFFFFFFFu - idx);
    }
}

// hist on logit bins (only bins >= LOWBIN) + opportunistic gather (bin >= STATIC_BIN)
// relies on g_hist/g_cnt being zero (static init on call 1; tails of
// k_mask/k_scan re-zero them for every subsequent call)
__global__ void k_hist(const float4* __restrict__ logits){
    int n = blockIdx.y;
    int t = blockIdx.x*blockDim.x + threadIdx.x;
    if (t >= AHW4) return;
    float4 v = logits[(size_t)n*AHW4 + t];
    float vv[4] = {v.x, v.y, v.z, v.w};
    #pragma unroll
    for (int k = 0; k < 4; k++){
        unsigned bin = lkey(vv[k]) >> 16;
        if (bin >= LOWBIN){
            atomicAdd(&g_hist[n*NBINS + bin], 1u);
            if (bin >= STATIC_BIN) emit_cand(n, vv[k], t*4 + k);
        }
    }
}

__device__ __forceinline__ void ce_reg(unsigned long long &a, unsigned long long &b, bool desc){
    if (desc ? (a < b) : (a > b)){ unsigned long long t=a; a=b; b=t; }
}

// stages j = jmax..1 (jmax <= 64) on the 128-element block b, warp-local
__device__ __forceinline__ void reg_stages(unsigned long long r[4], int b, int lane,
                                           int ksz, int jmax){
    if (jmax >= 64){
        bool d0 = (((b*128 + 0*32 + lane) & ksz) == 0);
        bool d1 = (((b*128 + 1*32 + lane) & ksz) == 0);
        ce_reg(r[0], r[2], d0);
        ce_reg(r[1], r[3], d1);
    }
    if (jmax >= 32){
        bool d0 = (((b*128 + 0*32 + lane) & ksz) == 0);
        bool d2 = (((b*128 + 2*32 + lane) & ksz) == 0);
        ce_reg(r[0], r[1], d0);
        ce_reg(r[2], r[3], d2);
    }
    int js = (jmax < 16) ? jmax : 16;
    for (int j = js; j >= 1; j >>= 1){
        #pragma unroll
        for (int k = 0; k < 4; k++){
            unsigned long long partner = __shfl_xor_sync(0xFFFFFFFFu, r[k], j);
            int idx_low = b*128 + k*32 + (lane & ~j);
            bool desc = ((idx_low & ksz) == 0);
            bool lower = ((lane & j) == 0);
            bool take_max = (lower == desc);
            r[k] = take_max ? (r[k] > partner ? r[k] : partner)
                            : (r[k] < partner ? r[k] : partner);
        }
    }
}

// thresh + (fallback gather) + bitonic sort + decode, one block per batch
__global__ __launch_bounds__(1024) void k_sortdecode(const float4* __restrict__ logits,
                             const float* __restrict__ regs,
                             const float* __restrict__ anchors,
                             const int*   __restrict__ sizes){
    int n = blockIdx.x;
    int tid = threadIdx.x;   // 1024 threads = 32 warps
    int lane = tid & 31;
    int b    = tid >> 5;     // warp id = 128-element block id
    __shared__ unsigned long long s[CAP];
    __shared__ unsigned wsuf[32];
    __shared__ int tstar, sh_thr, sh_fast, sh_cnt;

    // ---- threshold from histogram (suffix scan; rare low-bin rebuild) ----
    for (int pass = 0; pass < 2; pass++){
        unsigned* seg = (unsigned*)s;
        const uint4* hp = (const uint4*)(g_hist + n*NBINS + tid*64);
        unsigned acc = 0;
        #pragma unroll
        for (int k=0;k<16;k++){ uint4 v = hp[k]; acc += v.x+v.y+v.z+v.w; }
        unsigned a = acc;
        #pragma unroll
        for (int off=1; off<32; off<<=1){
            unsigned v = __shfl_down_sync(0xFFFFFFFFu, a, off);
            if (lane < 32-off) a += v;
        }
        if (lane == 0) wsuf[b] = a;
        __syncthreads();
        if (tid < 32){
            unsigned w = wsuf[tid];
            #pragma unroll
            for (int off=1; off<32; off<<=1){
                unsigned v = __shfl_down_sync(0xFFFFFFFFu, w, off);
                if (tid < 32-off) w += v;
            }
            wsuf[tid] = w;
        }
        __syncthreads();
        unsigned total = wsuf[0];
        if (total >= PRE){
            unsigned suf = a + ((b < 31) ? wsuf[b+1] : 0u);
            seg[tid] = suf;
            __syncthreads();
            if (suf >= PRE && (tid==1023 || seg[tid+1] < PRE)) tstar = tid;
            __syncthreads();
            if (tid==0){
                int t = tstar;
                unsigned cum = (t < 1023) ? seg[t+1] : 0u;
                int T = t*64;
                for (int bb = t*64+63; bb >= t*64; bb--){
                    cum += g_hist[n*NBINS + bb];
                    if (cum >= PRE){ T = bb; break; }
                }
                int thrv = (T > 0) ? (T - 1) : 0;      // one-bin safety margin
                int cnt0 = atomicAdd(&g_cnt[n], 0);
                bool fast = (STATIC_BIN <= thrv) && (cnt0 <= CAP);
                sh_thr = thrv; sh_fast = fast ? 1 : 0; sh_cnt = cnt0;
                if (!fast) atomicExch(&g_cnt[n], 0);   // re-gather from scratch
            }
            __syncthreads();
            break;
        }
        // pathological: rebuild the skipped low bins exactly, then rescan
        for (int t = tid; t < AHW4; t += 1024){
            float4 v = logits[(size_t)n*AHW4 + t];
            float vv[4] = {v.x, v.y, v.z, v.w};
            #pragma unroll
            for (int k=0;k<4;k++){
                unsigned bin = lkey(vv[k]) >> 16;
                if (bin < LOWBIN) atomicAdd(&g_hist[n*NBINS + bin], 1u);
            }
        }
        __syncthreads();
    }

    // ---- fallback gather (only if static pre-gather was insufficient) ----
    if (!sh_fast){
        int thr = sh_thr;
        for (int t = tid; t < AHW4; t += 1024){
            float4 v = logits[(size_t)n*AHW4 + t];
            float vv[4] = {v.x, v.y, v.z, v.w};
            #pragma unroll
            for (int k=0;k<4;k++){
                if ((int)(lkey(vv[k]) >> 16) >= thr) emit_cand(n, vv[k], t*4 + k);
            }
        }
        __syncthreads();
        if (tid == 0) sh_cnt = atomicAdd(&g_cnt[n], 0);
        __syncthreads();
    }

    int cnt = sh_cnt; if (cnt > CAP) cnt = CAP;
    for (int k = tid; k < CAP; k += 1024)
        s[k] = (k < cnt) ? g_cand[n*CAP + k] : 0ull;
    __syncthreads();

    // Phase A: all ksz=2..128 stages, warp-local (registers + shfl)
    {
        unsigned long long r[4];
        #pragma unroll
        for (int k = 0; k < 4; k++) r[k] = s[b*128 + k*32 + lane];
        #pragma unroll
        for (int ksz = 2; ksz <= 128; ksz <<= 1)
            reg_stages(r, b, lane, ksz, ksz >> 1);
        #pragma unroll
        for (int k = 0; k < 4; k++) s[b*128 + k*32 + lane] = r[k];
    }
    __syncthreads();

    // Phase B: ksz = 256..4096; paired smem stages for j>=128, reg phase j<=64
    for (int ksz = 256; ksz <= CAP; ksz <<= 1){
        int j = ksz >> 1;
        while (j >= 256){
            int j1 = j, j2 = j >> 1;
            int s2 = __ffs(j2) - 1;
            int c = tid;                                  // 1024 groups of 4
            int idx = ((c >> s2) << (s2+2)) | (c & (j2-1));
            unsigned long long e0 = s[idx];
            unsigned long long e1 = s[idx + j2];
            unsigned long long e2 = s[idx + j1];
            unsigned long long e3 = s[idx + j1 + j2];
            bool desc = ((idx & ksz) == 0);
            ce_reg(e0, e2, desc); ce_reg(e1, e3, desc);   // stage j1
            ce_reg(e0, e1, desc); ce_reg(e2, e3, desc);   // stage j2
            s[idx] = e0; s[idx + j2] = e1; s[idx + j1] = e2; s[idx + j1 + j2] = e3;
            __syncthreads();
            j >>= 2;
        }
        if (j == 128){
            #pragma unroll
            for (int t = 0; t < 2; t++){
                int c = tid + t*1024;
                int idx = ((c >> 7) << 8) | (c & 127);
                int p = idx | 128;
                unsigned long long a = s[idx], bb2 = s[p];
                bool desc = ((idx & ksz) == 0);
                if (desc ? (a < bb2) : (a > bb2)){ s[idx] = bb2; s[p] = a; }
            }
            __syncthreads();
        }
        {
            unsigned long long r[4];
            #pragma unroll
            for (int k = 0; k < 4; k++) r[k] = s[b*128 + k*32 + lane];
            reg_stages(r, b, lane, ksz, 64);
            #pragma unroll
            for (int k = 0; k < 4; k++) s[b*128 + k*32 + lane] = r[k];
        }
        __syncthreads();
    }

    float fh = (float)sizes[n*2+0];
    float fw = (float)sizes[n*2+1];
    for (int r = tid; r < PRE; r += 1024){
        unsigned long long v = s[r];
        unsigned key = (unsigned)(v >> 32);
        unsigned idx = 0xFFFFFFFFu - (unsigned)(v & 0xFFFFFFFFull);
        float score = __uint_as_float(key ^ 0x80000000u);
        float4 anc = ((const float4*)anchors)[(size_t)n*AHW + idx];
        int a = (int)(idx % (unsigned)AA);
        int pix = (int)(idx / (unsigned)AA);
        const float* rb = regs + (size_t)n*(AA*4*HWP) + (size_t)a*4*HWP + pix;
        float r0 = rb[0];
        float r1 = rb[HWP];
        float r2 = rb[2*HWP];
        float r3 = rb[3*HWP];
        float ws = anc.z - anc.x + 1.0f;
        float hs = anc.w - anc.y + 1.0f;
        float xc = anc.x + 0.5f*ws;
        float yc = anc.y + 0.5f*hs;
        float dw = fminf(r2, MAXOFF);
        float dh = fminf(r3, MAXOFF);
        xc = xc + r0*ws;
        yc = yc + r1*hs;
        ws = ws * expf(dw);
        hs = hs * expf(dh);
        float x1 = xc - 0.5f*ws;
        float y1 = yc - 0.5f*hs;
        float x2 = xc + 0.5f*ws - 1.0f;
        float y2 = yc + 0.5f*hs - 1.0f;
        x1 = fminf(fmaxf(x1, 0.0f), fw - 1.0f);
        y1 = fminf(fmaxf(y1, 0.0f), fh - 1.0f);
        x2 = fminf(fmaxf(x2, 0.0f), fw - 1.0f);
        y2 = fminf(fmaxf(y2, 0.0f), fh - 1.0f);
        g_boxes[n*PRE + r] = make_float4(x1,y1,x2,y2);
        g_sc[n*PRE + r] = score;
    }
}

// Upper-triangle tile IoU mask. grid = (528, NB), 256 threads.
// Tail: re-zero g_hist for the next call.
__global__ void k_mask(){
    int n = blockIdx.y;
    int p = blockIdx.x;
    int ti = 0;
    while (p >= 32 - ti){ p -= 32 - ti; ti++; }
    int tj = ti + p;

    __shared__ float4 rb[64];
    __shared__ float4 cb[64];
    __shared__ float  ca[64];
    int tid = threadIdx.x;
    if (tid < 64){
        int gi = ti*64 + tid;
        rb[tid] = (gi < PRE) ? g_boxes[n*PRE + gi] : make_float4(0.f,0.f,-1.f,-1.f);
    } else if (tid < 128){
        int t = tid - 64;
        int gj = tj*64 + t;
        float4 b = (gj < PRE) ? g_boxes[n*PRE + gj] : make_float4(0.f,0.f,-1.f,-1.f);
        cb[t] = b;
        ca[t] = (b.z - b.x + 1.0f) * (b.w - b.y + 1.0f);
    }
    __syncthreads();

    int rid = tid >> 3;       // 0..31
    int q   = tid & 7;
    int iA = ti*64 + rid;
    int iB = iA + 32;
    float4 bA = rb[rid];
    float4 bB = rb[rid + 32];
    float aA = (bA.z - bA.x + 1.0f) * (bA.w - bA.y + 1.0f);
    float aB = (bB.z - bB.x + 1.0f) * (bB.w - bB.y + 1.0f);

    unsigned long long wA = 0ull, wB = 0ull;
    #pragma unroll
    for (int jj = 0; jj < 8; jj++){
        int j = jj*8 + q;            // strided -> conflict-free LDS across q
        int jg = tj*64 + j;
        if (jg >= PRE) continue;
        float4 bj = cb[j];
        float aj = ca[j];
        float xtlA = fmaxf(bA.x, bj.x), ytlA = fmaxf(bA.y, bj.y);
        float xbrA = fminf(bA.z, bj.z), ybrA = fminf(bA.w, bj.w);
        float iwA = fmaxf(xbrA - xtlA + 1.0f, 0.0f);
        float ihA = fmaxf(ybrA - ytlA + 1.0f, 0.0f);
        float interA = iwA * ihA;
        float denomA = aA + aj - interA;
        if (jg > iA && interA > 0.6f * denomA)
            if (interA / denomA > THR) wA |= (1ull << j);
        float xtlB = fmaxf(bB.x, bj.x), ytlB = fmaxf(bB.y, bj.y);
        float xbrB = fminf(bB.z, bj.z), ybrB = fminf(bB.w, bj.w);
        float iwB = fmaxf(xbrB - xtlB + 1.0f, 0.0f);
        float ihB = fmaxf(ybrB - ytlB + 1.0f, 0.0f);
        float interB = iwB * ihB;
        float denomB = aB + aj - interB;
        if (jg > iB && interB > 0.6f * denomB)
            if (interB / denomB > THR) wB |= (1ull << j);
    }
    wA |= __shfl_xor_sync(0xFFFFFFFFu, wA, 1, 8);
    wA |= __shfl_xor_sync(0xFFFFFFFFu, wA, 2, 8);
    wA |= __shfl_xor_sync(0xFFFFFFFFu, wA, 4, 8);
    wB |= __shfl_xor_sync(0xFFFFFFFFu, wB, 1, 8);
    wB |= __shfl_xor_sync(0xFFFFFFFFu, wB, 2, 8);
    wB |= __shfl_xor_sync(0xFFFFFFFFu, wB, 4, 8);
    if (q == 0){
        if (iA < PRE) g_mask[((size_t)n*ROWS_PAD + iA)*MW + tj] = wA;
        if (iB < PRE) g_mask[((size_t)n*ROWS_PAD + iB)*MW + tj] = wB;
    }

    // tail: zero g_hist for the next call (independent of this kernel's data)
    unsigned gid = (blockIdx.y*gridDim.x + blockIdx.x)*blockDim.x + threadIdx.x;
    if (gid < (unsigned)(NB*NBINS/4))
        ((uint4*)g_hist)[gid] = make_uint4(0,0,0,0);
}

// Warp-specialized pipelined NMS scan: warp 0 = chain + quick-OR (critical
// path); warps 1-15 = bulk OR of previous block + tile staging. 1 bar/iter.
#define TS 33
__global__ __launch_bounds__(512) void k_scan(float* __restrict__ out){
    int n = blockIdx.x;
    int tid = threadIdx.x;    // 512 = 16 warps
    int lane = tid & 31;
    int wrp  = tid >> 5;
    __shared__ unsigned long long remv[MW];
    __shared__ unsigned long long tile[3][64*TS];
    __shared__ unsigned long long sh_alive[2];
    __shared__ int sh_stop;
    __shared__ int kb[MW+1];
    if (tid < MW) remv[tid] = 0ull;
    if (tid == 0) sh_stop = MW;

    const unsigned long long* gbase = &g_mask[((size_t)n*ROWS_PAD)*MW];
    // stage tile 0 (all threads)
    #pragma unroll
    for (int q = 0; q < 4; q++){
        int k = tid + q*512;
        tile[0][(k >> 5)*TS + (k & 31)] = gbase[k];
    }
    // prefetch tile 1 (warps 1..15 only; same mapping used for store)
    unsigned long long pf[5];
    int ptid = tid - 32;      // 0..479 for warps 1..15
    if (wrp > 0){
        #pragma unroll
        for (int q = 0; q < 5; q++){
            int k = ptid + q*480;
            if (k < 64*MW) pf[q] = gbase[64*MW + k];
        }
    }
    __syncthreads();

    int kept_total = 0;       // maintained by warp0 lane0 only
    for (int blk = 0; blk < MW; blk++){
        int cur   = blk % 3;
        int stbuf = (blk+1) % 3;
        int prev  = (blk+2) % 3;        // == (blk-1) % 3
        int base = blk*64;
        int nrows = PRE - base; if (nrows > 64) nrows = 64;

        if (wrp == 0){
            // --- serial chain (lane 0), branchless, pipelined loads ---
            if (lane == 0){
                unsigned long long w0 = remv[blk];
                const unsigned long long* tp = &tile[cur][blk];
                unsigned long long bufA[8], bufB[8];
                #pragma unroll
                for (int k = 0; k < 8; k++) bufA[k] = tp[k*TS];
                #pragma unroll
                for (int c = 0; c < 8; c++){
                    if (c < 7){
                        #pragma unroll
                        for (int k = 0; k < 8; k++){
                            if (c & 1) bufA[k] = tp[((c+1)*8 + k)*TS];
                            else       bufB[k] = tp[((c+1)*8 + k)*TS];
                        }
                    }
                    #pragma unroll
                    for (int k = 0; k < 8; k++){
                        int rr = c*8 + k;
                        unsigned long long m = (c & 1) ? bufB[k] : bufA[k];
                        unsigned long long msk = ((w0 >> rr) & 1ull) - 1ull; // ~0 if alive
                        w0 |= m & msk;
                    }
                }
                remv[blk] = w0;
                unsigned long long validm = (nrows == 64) ? ~0ull : ((1ull << nrows) - 1ull);
                unsigned long long alive = (~w0) & validm;   // bit rr final at step rr
                sh_alive[blk & 1] = alive;
                kept_total += __popcll(alive);
                if (kept_total >= POST && blk + 1 < MW) sh_stop = blk + 1;
            }
            __syncwarp();
            // --- quick OR: block blk's alive rows onto word blk+1 ---
            if (blk + 1 < MW){
                unsigned long long alive = sh_alive[blk & 1];
                unsigned long long acc = 0ull;
                if ((alive >> lane) & 1ull)        acc  = tile[cur][lane*TS + (blk+1)];
                if ((alive >> (lane+32)) & 1ull)   acc |= tile[cur][(lane+32)*TS + (blk+1)];
                acc |= __shfl_xor_sync(0xFFFFFFFFu, acc, 16);
                acc |= __shfl_xor_sync(0xFFFFFFFFu, acc, 8);
                acc |= __shfl_xor_sync(0xFFFFFFFFu, acc, 4);
                acc |= __shfl_xor_sync(0xFFFFFFFFu, acc, 2);
                acc |= __shfl_xor_sync(0xFFFFFFFFu, acc, 1);
                if (lane == 0 && acc) atomicOr(&remv[blk+1], acc);
            }
        } else {
            // --- store prefetched tile blk+1 ---
            if (blk + 1 < MW){
                #pragma unroll
                for (int q = 0; q < 5; q++){
                    int k = ptid + q*480;
                    if (k < 64*MW) tile[stbuf][(k >> 5)*TS + (k & 31)] = pf[q];
                }
            }
            // --- issue prefetch for tile blk+2 ---
            if (blk + 2 < MW){
                const unsigned long long* gp = gbase + (size_t)(blk+2)*64*MW;
                #pragma unroll
                for (int q = 0; q < 5; q++){
                    int k = ptid + q*480;
                    if (k < 64*MW) pf[q] = gp[k];
                }
            }
            // --- bulk OR: block blk-1's alive rows onto words >= blk+1 ---
            if (blk >= 1 && lane >= blk+1){
                unsigned long long alive = sh_alive[(blk-1) & 1];
                unsigned long long acc = 0ull;
                for (int rr = wrp - 1; rr < 64; rr += 15){
                    if ((alive >> rr) & 1ull) acc |= tile[prev][rr*TS + lane];
                }
                if (acc) atomicOr(&remv[lane], acc);
            }
        }
        __syncthreads();
        if (blk + 1 >= sh_stop) break;     // kept >= POST: rest irrelevant
    }

    if (tid == 0){
        int c = 0;
        for (int ww = 0; ww < MW; ww++){
            kb[ww] = c;
            unsigned long long valid = (ww == MW-1) ? 0xFFFFull : ~0ull;
            c += __popcll((~remv[ww]) & valid);
        }
        kb[MW] = c;
        g_cnt[n] = 0;           // tail: reset candidate counter for next call
    }
    __syncthreads();
    // stable partition: kept (in order) then suppressed (in order) == post top_k
    for (int i = tid; i < PRE; i += 512){
        int ww = i >> 6, b = i & 63;
        unsigned long long valid = (ww == MW-1) ? 0xFFFFull : ~0ull;
        unsigned long long notr = (~remv[ww]) & valid;
        bool keep = (notr >> b) & 1ull;
        unsigned long long below = b ? (notr & ((~0ull) >> (64 - b))) : 0ull;
        int kbelow = kb[ww] + __popcll(below);
        int pos = keep ? kbelow : (kb[MW] + (i - kbelow));
        if (pos < POST){
            float4 bx = g_boxes[n*PRE + i];
            float sc = keep ? g_sc[n*PRE + i] : -1.0f;
            float* op = out + ((size_t)n*POST + pos)*5;
            op[0]=bx.x; op[1]=bx.y; op[2]=bx.z; op[3]=bx.w; op[4]=sc;
        }
    }
}

extern "C" void kernel_launch(void* const* d_in, const int* in_sizes, int n_in,
                              void* d_out, int out_size){
    (void)in_sizes; (void)n_in; (void)out_size;
    const float* logits  = (const float*)d_in[0];
    const float* regs    = (const float*)d_in[1];
    const float* anchors = (const float*)d_in[2];
    const int*   sizes   = (const int*)d_in[3];
    float* out = (float*)d_out;

    dim3 g((AHW4 + 255)/256, NB);
    k_hist<<<g, 256>>>((const float4*)logits);
    k_sortdecode<<<NB, 1024>>>((const float4*)logits, regs, anchors, sizes);
    k_mask<<<dim3(528, NB), 256>>>();
    k_scan<<<NB, 512>>>(out);
}

// round 10
// speedup vs baseline: 12.5371x; 1.0675x over previous
#include <cuda_runtime.h>
#include <math.h>

#define NB 8
#define AA 3
#define HH 200
#define WW 336
#define HWP (HH*WW)          // 67200
#define AHW (AA*HWP)         // 201600
#define AHW4 (AHW/4)         // 50400
#define PRE 2000
#define POST 1000
#define THR 0.7f
#define MAXOFF 4.135166556742356f
#define CAP 4096
#define NBINS 65536
#define STATIC_BIN 49164     // logit-key bin of ~2.1875 (score ~0.9)
#define LOWSCAN 49152        // logit-key bin of 2.0 -- hist/scan window start
#define MW 32
#define ROWS_PAD 2048

__device__ unsigned int        g_hist[NB*NBINS];
__device__ int                 g_cnt[NB];
__device__ unsigned long long  g_cand[NB*CAP];
__device__ float4              g_boxes[NB*PRE];
__device__ float               g_sc[NB*PRE];
// row-major: g_mask[n][row][word], only words w >= row/64 are valid
__device__ unsigned long long  g_mask[(size_t)NB*ROWS_PAD*MW];

// orderable key of raw logit (monotone with sigmoid)
__device__ __forceinline__ unsigned lkey(float x){
    unsigned b = __float_as_uint(x);
    return (b & 0x80000000u) ? ~b : (b | 0x80000000u);
}

// exact reference score key (sigmoid), computed only for candidates
__device__ __forceinline__ unsigned skey(float x){
    float s = 1.0f/(1.0f + expf(-x));
    return __float_as_uint(s) | 0x80000000u;   // s > 0 -> orderable
}

__device__ __forceinline__ void emit_cand(int n, float x, int el){
    int pos = atomicAdd(&g_cnt[n], 1);
    if (pos < CAP){
        int a = el / HWP;
        int pix = el - a*HWP;
        unsigned idx = (unsigned)(pix*AA + a);     // score-space index
        g_cand[n*CAP + pos] =
            ((unsigned long long)skey(x) << 32) | (unsigned long long)(0xFFFFFFFFu - idx);
    }
}

// hist on logit bins (only bins >= LOWSCAN) + opportunistic gather (bin >= STATIC_BIN)
__global__ void k_hist(const float4* __restrict__ logits){
    int n = blockIdx.y;
    int t = blockIdx.x*blockDim.x + threadIdx.x;
    if (t >= AHW4) return;
    float4 v = logits[(size_t)n*AHW4 + t];
    float vv[4] = {v.x, v.y, v.z, v.w};
    #pragma unroll
    for (int k = 0; k < 4; k++){
        unsigned bin = lkey(vv[k]) >> 16;
        if (bin >= LOWSCAN){
            atomicAdd(&g_hist[n*NBINS + bin], 1u);
            if (bin >= STATIC_BIN) emit_cand(n, vv[k], t*4 + k);
        }
    }
}

__device__ __forceinline__ void ce_reg(unsigned long long &a, unsigned long long &b, bool desc){
    if (desc ? (a < b) : (a > b)){ unsigned long long t=a; a=b; b=t; }
}

// stages j = jmax..1 (jmax <= 64) on the 128-element block b, warp-local
__device__ __forceinline__ void reg_stages(unsigned long long r[4], int b, int lane,
                                           int ksz, int jmax){
    if (jmax >= 64){
        bool d0 = (((b*128 + 0*32 + lane) & ksz) == 0);
        bool d1 = (((b*128 + 1*32 + lane) & ksz) == 0);
        ce_reg(r[0], r[2], d0);
        ce_reg(r[1], r[3], d1);
    }
    if (jmax >= 32){
        bool d0 = (((b*128 + 0*32 + lane) & ksz) == 0);
        bool d2 = (((b*128 + 2*32 + lane) & ksz) == 0);
        ce_reg(r[0], r[1], d0);
        ce_reg(r[2], r[3], d2);
    }
    int js = (jmax < 16) ? jmax : 16;
    for (int j = js; j >= 1; j >>= 1){
        #pragma unroll
        for (int k = 0; k < 4; k++){
            unsigned long long partner = __shfl_xor_sync(0xFFFFFFFFu, r[k], j);
            int idx_low = b*128 + k*32 + (lane & ~j);
            bool desc = ((idx_low & ksz) == 0);
            bool lower = ((lane & j) == 0);
            bool take_max = (lower == desc);
            r[k] = take_max ? (r[k] > partner ? r[k] : partner)
                            : (r[k] < partner ? r[k] : partner);
        }
    }
}

// thresh + filter + (fallback gather) + adaptive bitonic sort + decode
__global__ __launch_bounds__(1024) void k_sortdecode(const float4* __restrict__ logits,
                             const float* __restrict__ regs,
                             const float* __restrict__ anchors,
                             const int*   __restrict__ sizes){
    int n = blockIdx.x;
    int tid = threadIdx.x;   // 1024 threads = 32 warps
    int lane = tid & 31;
    int b    = tid >> 5;     // warp id = 128-element block id
    __shared__ unsigned long long s[CAP];
    __shared__ unsigned wsuf[32];
    __shared__ unsigned sh_skth;
    __shared__ int tstar, sh_thr, sh_fast, sh_cnt, fcnt;

    // ---- threshold from histogram (windowed scan; rare full rebuild) ----
    for (int pass = 0; pass < 2; pass++){
        unsigned* seg = (unsigned*)s;
        int per = pass ? 64 : 16;              // bins per thread
        int base_bin = pass ? 0 : LOWSCAN;
        const uint4* hp = (const uint4*)(g_hist + n*NBINS + base_bin + tid*per);
        unsigned acc = 0;
        for (int k = 0; k < per/4; k++){ uint4 v = hp[k]; acc += v.x+v.y+v.z+v.w; }
        unsigned a = acc;
        #pragma unroll
        for (int off=1; off<32; off<<=1){
            unsigned v = __shfl_down_sync(0xFFFFFFFFu, a, off);
            if (lane < 32-off) a += v;
        }
        if (lane == 0) wsuf[b] = a;
        __syncthreads();
        if (tid < 32){
            unsigned w = wsuf[tid];
            #pragma unroll
            for (int off=1; off<32; off<<=1){
                unsigned v = __shfl_down_sync(0xFFFFFFFFu, w, off);
                if (tid < 32-off) w += v;
            }
            wsuf[tid] = w;
        }
        __syncthreads();
        unsigned total = wsuf[0];
        if (total >= PRE){
            unsigned suf = a + ((b < 31) ? wsuf[b+1] : 0u);
            seg[tid] = suf;
            __syncthreads();
            if (suf >= PRE && (tid==1023 || seg[tid+1] < PRE)) tstar = tid;
            __syncthreads();
            if (tid==0){
                int t = tstar;
                unsigned cum = (t < 1023) ? seg[t+1] : 0u;
                int T = base_bin + t*per;
                for (int bb = t*per + per - 1; bb >= t*per; bb--){
                    cum += g_hist[n*NBINS + base_bin + bb];
                    if (cum >= PRE){ T = base_bin + bb; break; }
                }
                int thrv = (T > 0) ? (T - 1) : 0;      // one-bin safety margin
                int cnt0 = atomicAdd(&g_cnt[n], 0);
                bool fast = (STATIC_BIN <= thrv) && (cnt0 <= CAP);
                sh_thr = thrv; sh_fast = fast ? 1 : 0; sh_cnt = cnt0;
                if (fast){
                    // skey of lower logit edge of exact cutoff bin T, minus 64 ULP slack
                    unsigned Tb = (unsigned)(thrv + 1);
                    float L0 = __uint_as_float((Tb << 16) ^ 0x80000000u);
                    unsigned sk = skey(L0);
                    sh_skth = (sk > 64u) ? (sk - 64u) : 0u;
                } else {
                    atomicExch(&g_cnt[n], 0);          // re-gather from scratch
                }
                fcnt = 0;
            }
            __syncthreads();
            break;
        }
        // pathological: rebuild the skipped low bins exactly, then full rescan
        for (int t = tid; t < AHW4; t += 1024){
            float4 v = logits[(size_t)n*AHW4 + t];
            float vv[4] = {v.x, v.y, v.z, v.w};
            #pragma unroll
            for (int k=0;k<4;k++){
                unsigned bin = lkey(vv[k]) >> 16;
                if (bin < LOWSCAN) atomicAdd(&g_hist[n*NBINS + bin], 1u);
            }
        }
        __syncthreads();
    }

    int f;  // number of live entries in s
    if (sh_fast){
        // filter candidates by exact score-key threshold (provable superset)
        unsigned skth = sh_skth;
        int cnt = sh_cnt;
        for (int k = tid; k < cnt; k += 1024){
            unsigned long long v = g_cand[n*CAP + k];
            if ((unsigned)(v >> 32) >= skth){
                int p = atomicAdd(&fcnt, 1);
                s[p] = v;
            }
        }
        __syncthreads();
        f = fcnt;
        if (f < PRE){           // paranoia: filter too tight -> use all
            __syncthreads();
            for (int k = tid; k < cnt; k += 1024) s[k] = g_cand[n*CAP + k];
            f = cnt;
        }
    } else {
        // fallback gather with the exact histogram threshold
        int thr = sh_thr;
        for (int t = tid; t < AHW4; t += 1024){
            float4 v = logits[(size_t)n*AHW4 + t];
            float vv[4] = {v.x, v.y, v.z, v.w};
            #pragma unroll
            for (int k=0;k<4;k++){
                if ((int)(lkey(vv[k]) >> 16) >= thr) emit_cand(n, vv[k], t*4 + k);
            }
        }
        __syncthreads();
        if (tid == 0) sh_cnt = atomicAdd(&g_cnt[n], 0);
        __syncthreads();
        f = sh_cnt; if (f > CAP) f = CAP;
        for (int k = tid; k < f; k += 1024) s[k] = g_cand[n*CAP + k];
    }
    int SORTN = (f <= 2048) ? 2048 : CAP;
    for (int k = tid; k < SORTN; k += 1024) if (k >= f) s[k] = 0ull;
    __syncthreads();

    // Phase A: all ksz=2..128 stages, warp-local (registers + shfl)
    if (b < SORTN/128){
        unsigned long long r[4];
        #pragma unroll
        for (int k = 0; k < 4; k++) r[k] = s[b*128 + k*32 + lane];
        #pragma unroll
        for (int ksz = 2; ksz <= 128; ksz <<= 1)
            reg_stages(r, b, lane, ksz, ksz >> 1);
        #pragma unroll
        for (int k = 0; k < 4; k++) s[b*128 + k*32 + lane] = r[k];
    }
    __syncthreads();

    // Phase B: ksz = 256..SORTN; paired smem stages for j>=128, reg phase j<=64
    for (int ksz = 256; ksz <= SORTN; ksz <<= 1){
        int j = ksz >> 1;
        while (j >= 256){
            if (tid < SORTN/4){
                int j1 = j, j2 = j >> 1;
                int s2 = __ffs(j2) - 1;
                int c = tid;
                int idx = ((c >> s2) << (s2+2)) | (c & (j2-1));
                unsigned long long e0 = s[idx];
                unsigned long long e1 = s[idx + j2];
                unsigned long long e2 = s[idx + j1];
                unsigned long long e3 = s[idx + j1 + j2];
                bool desc = ((idx & ksz) == 0);
                ce_reg(e0, e2, desc); ce_reg(e1, e3, desc);   // stage j1
                ce_reg(e0, e1, desc); ce_reg(e2, e3, desc);   // stage j2
                s[idx] = e0; s[idx + j2] = e1; s[idx + j1] = e2; s[idx + j1 + j2] = e3;
            }
            __syncthreads();
            j >>= 2;
        }
        if (j == 128){
            for (int c = tid; c < SORTN/2; c += 1024){
                int idx = ((c >> 7) << 8) | (c & 127);
                int p = idx | 128;
                unsigned long long a = s[idx], bb2 = s[p];
                bool desc = ((idx & ksz) == 0);
                if (desc ? (a < bb2) : (a > bb2)){ s[idx] = bb2; s[p] = a; }
            }
            __syncthreads();
        }
        if (b < SORTN/128){
            unsigned long long r[4];
            #pragma unroll
            for (int k = 0; k < 4; k++) r[k] = s[b*128 + k*32 + lane];
            reg_stages(r, b, lane, ksz, 64);
            #pragma unroll
            for (int k = 0; k < 4; k++) s[b*128 + k*32 + lane] = r[k];
        }
        __syncthreads();
    }

    float fh = (float)sizes[n*2+0];
    float fw = (float)sizes[n*2+1];
    for (int r = tid; r < PRE; r += 1024){
        unsigned long long v = s[r];
        unsigned key = (unsigned)(v >> 32);
        unsigned idx = 0xFFFFFFFFu - (unsigned)(v & 0xFFFFFFFFull);
        float score = __uint_as_float(key ^ 0x80000000u);
        float4 anc = ((const float4*)anchors)[(size_t)n*AHW + idx];
        int a = (int)(idx % (unsigned)AA);
        int pix = (int)(idx / (unsigned)AA);
        const float* rb = regs + (size_t)n*(AA*4*HWP) + (size_t)a*4*HWP + pix;
        float r0 = rb[0];
        float r1 = rb[HWP];
        float r2 = rb[2*HWP];
        float r3 = rb[3*HWP];
        float ws = anc.z - anc.x + 1.0f;
        float hs = anc.w - anc.y + 1.0f;
        float xc = anc.x + 0.5f*ws;
        float yc = anc.y + 0.5f*hs;
        float dw = fminf(r2, MAXOFF);
        float dh = fminf(r3, MAXOFF);
        xc = xc + r0*ws;
        yc = yc + r1*hs;
        ws = ws * expf(dw);
        hs = hs * expf(dh);
        float x1 = xc - 0.5f*ws;
        float y1 = yc - 0.5f*hs;
        float x2 = xc + 0.5f*ws - 1.0f;
        float y2 = yc + 0.5f*hs - 1.0f;
        x1 = fminf(fmaxf(x1, 0.0f), fw - 1.0f);
        y1 = fminf(fmaxf(y1, 0.0f), fh - 1.0f);
        x2 = fminf(fmaxf(x2, 0.0f), fw - 1.0f);
        y2 = fminf(fmaxf(y2, 0.0f), fh - 1.0f);
        g_boxes[n*PRE + r] = make_float4(x1,y1,x2,y2);
        g_sc[n*PRE + r] = score;
    }
}

// Upper-triangle tile IoU mask. grid = (528, NB), 256 threads.
// Tail: re-zero g_hist for the next call.
__global__ void k_mask(){
    int n = blockIdx.y;
    int p = blockIdx.x;
    int ti = 0;
    while (p >= 32 - ti){ p -= 32 - ti; ti++; }
    int tj = ti + p;

    __shared__ float4 rb[64];
    __shared__ float4 cb[64];
    __shared__ float  ca[64];
    int tid = threadIdx.x;
    if (tid < 64){
        int gi = ti*64 + tid;
        rb[tid] = (gi < PRE) ? g_boxes[n*PRE + gi] : make_float4(0.f,0.f,-1.f,-1.f);
    } else if (tid < 128){
        int t = tid - 64;
        int gj = tj*64 + t;
        float4 b = (gj < PRE) ? g_boxes[n*PRE + gj] : make_float4(0.f,0.f,-1.f,-1.f);
        cb[t] = b;
        ca[t] = (b.z - b.x + 1.0f) * (b.w - b.y + 1.0f);
    }
    __syncthreads();

    int rid = tid >> 3;       // 0..31
    int q   = tid & 7;
    int iA = ti*64 + rid;
    int iB = iA + 32;
    float4 bA = rb[rid];
    float4 bB = rb[rid + 32];
    float aA = (bA.z - bA.x + 1.0f) * (bA.w - bA.y + 1.0f);
    float aB = (bB.z - bB.x + 1.0f) * (bB.w - bB.y + 1.0f);

    unsigned long long wA = 0ull, wB = 0ull;
    #pragma unroll
    for (int jj = 0; jj < 8; jj++){
        int j = jj*8 + q;            // strided -> conflict-free LDS across q
        int jg = tj*64 + j;
        if (jg >= PRE) continue;
        float4 bj = cb[j];
        float aj = ca[j];
        float xtlA = fmaxf(bA.x, bj.x), ytlA = fmaxf(bA.y, bj.y);
        float xbrA = fminf(bA.z, bj.z), ybrA = fminf(bA.w, bj.w);
        float iwA = fmaxf(xbrA - xtlA + 1.0f, 0.0f);
        float ihA = fmaxf(ybrA - ytlA + 1.0f, 0.0f);
        float interA = iwA * ihA;
        float denomA = aA + aj - interA;
        if (jg > iA && interA > 0.6f * denomA)
            if (interA / denomA > THR) wA |= (1ull << j);
        float xtlB = fmaxf(bB.x, bj.x), ytlB = fmaxf(bB.y, bj.y);
        float xbrB = fminf(bB.z, bj.z), ybrB = fminf(bB.w, bj.w);
        float iwB = fmaxf(xbrB - xtlB + 1.0f, 0.0f);
        float ihB = fmaxf(ybrB - ytlB + 1.0f, 0.0f);
        float interB = iwB * ihB;
        float denomB = aB + aj - interB;
        if (jg > iB && interB > 0.6f * denomB)
            if (interB / denomB > THR) wB |= (1ull << j);
    }
    wA |= __shfl_xor_sync(0xFFFFFFFFu, wA, 1, 8);
    wA |= __shfl_xor_sync(0xFFFFFFFFu, wA, 2, 8);
    wA |= __shfl_xor_sync(0xFFFFFFFFu, wA, 4, 8);
    wB |= __shfl_xor_sync(0xFFFFFFFFu, wB, 1, 8);
    wB |= __shfl_xor_sync(0xFFFFFFFFu, wB, 2, 8);
    wB |= __shfl_xor_sync(0xFFFFFFFFu, wB, 4, 8);
    if (q == 0){
        if (iA < PRE) g_mask[((size_t)n*ROWS_PAD + iA)*MW + tj] = wA;
        if (iB < PRE) g_mask[((size_t)n*ROWS_PAD + iB)*MW + tj] = wB;
    }

    // tail: zero g_hist for the next call (independent of this kernel's data)
    unsigned gid = (blockIdx.y*gridDim.x + blockIdx.x)*blockDim.x + threadIdx.x;
    if (gid < (unsigned)(NB*NBINS/4))
        ((uint4*)g_hist)[gid] = make_uint4(0,0,0,0);
}

// Warp-specialized pipelined NMS scan: warp 0 = chain + quick-OR (critical
// path); warps 1-15 = bulk OR of previous block + tile staging. 1 bar/iter.
#define TS 33
__global__ __launch_bounds__(512) void k_scan(float* __restrict__ out){
    int n = blockIdx.x;
    int tid = threadIdx.x;    // 512 = 16 warps
    int lane = tid & 31;
    int wrp  = tid >> 5;
    __shared__ unsigned long long remv[MW];
    __shared__ unsigned long long tile[3][64*TS];
    __shared__ unsigned long long sh_alive[2];
    __shared__ int sh_stop;
    __shared__ int kb[MW+1];
    if (tid < MW) remv[tid] = 0ull;
    if (tid == 0) sh_stop = MW;

    const unsigned long long* gbase = &g_mask[((size_t)n*ROWS_PAD)*MW];
    #pragma unroll
    for (int q = 0; q < 4; q++){
        int k = tid + q*512;
        tile[0][(k >> 5)*TS + (k & 31)] = gbase[k];
    }
    unsigned long long pf[5];
    int ptid = tid - 32;      // 0..479 for warps 1..15
    if (wrp > 0){
        #pragma unroll
        for (int q = 0; q < 5; q++){
            int k = ptid + q*480;
            if (k < 64*MW) pf[q] = gbase[64*MW + k];
        }
    }
    __syncthreads();

    int kept_total = 0;       // maintained by warp0 lane0 only
    for (int blk = 0; blk < MW; blk++){
        int cur   = blk % 3;
        int stbuf = (blk+1) % 3;
        int prev  = (blk+2) % 3;
        int base = blk*64;
        int nrows = PRE - base; if (nrows > 64) nrows = 64;

        if (wrp == 0){
            if (lane == 0){
                unsigned long long w0 = remv[blk];
                const unsigned long long* tp = &tile[cur][blk];
                unsigned long long bufA[8], bufB[8];
                #pragma unroll
                for (int k = 0; k < 8; k++) bufA[k] = tp[k*TS];
                #pragma unroll
                for (int c = 0; c < 8; c++){
                    if (c < 7){
                        #pragma unroll
                        for (int k = 0; k < 8; k++){
                            if (c & 1) bufA[k] = tp[((c+1)*8 + k)*TS];
                            else       bufB[k] = tp[((c+1)*8 + k)*TS];
                        }
                    }
                    #pragma unroll
                    for (int k = 0; k < 8; k++){
                        int rr = c*8 + k;
                        unsigned long long m = (c & 1) ? bufB[k] : bufA[k];
                        unsigned long long msk = ((w0 >> rr) & 1ull) - 1ull;
                        w0 |= m & msk;
                    }
                }
                remv[blk] = w0;
                unsigned long long validm = (nrows == 64) ? ~0ull : ((1ull << nrows) - 1ull);
                unsigned long long alive = (~w0) & validm;
                sh_alive[blk & 1] = alive;
                kept_total += __popcll(alive);
                if (kept_total >= POST && blk + 1 < MW) sh_stop = blk + 1;
            }
            __syncwarp();
            if (blk + 1 < MW){
                unsigned long long alive = sh_alive[blk & 1];
                unsigned long long acc = 0ull;
                if ((alive >> lane) & 1ull)        acc  = tile[cur][lane*TS + (blk+1)];
                if ((alive >> (lane+32)) & 1ull)   acc |= tile[cur][(lane+32)*TS + (blk+1)];
                acc |= __shfl_xor_sync(0xFFFFFFFFu, acc, 16);
                acc |= __shfl_xor_sync(0xFFFFFFFFu, acc, 8);
                acc |= __shfl_xor_sync(0xFFFFFFFFu, acc, 4);
                acc |= __shfl_xor_sync(0xFFFFFFFFu, acc, 2);
                acc |= __shfl_xor_sync(0xFFFFFFFFu, acc, 1);
                if (lane == 0 && acc) atomicOr(&remv[blk+1], acc);
            }
        } else {
            if (blk + 1 < MW){
                #pragma unroll
                for (int q = 0; q < 5; q++){
                    int k = ptid + q*480;
                    if (k < 64*MW) tile[stbuf][(k >> 5)*TS + (k & 31)] = pf[q];
                }
            }
            if (blk + 2 < MW){
                const unsigned long long* gp = gbase + (size_t)(blk+2)*64*MW;
                #pragma unroll
                for (int q = 0; q < 5; q++){
                    int k = ptid + q*480;
                    if (k < 64*MW) pf[q] = gp[k];
                }
            }
            if (blk >= 1 && lane >= blk+1){
                unsigned long long alive = sh_alive[(blk-1) & 1];
                unsigned long long acc = 0ull;
                for (int rr = wrp - 1; rr < 64; rr += 15){
                    if ((alive >> rr) & 1ull) acc |= tile[prev][rr*TS + lane];
                }
                if (acc) atomicOr(&remv[lane], acc);
            }
        }
        __syncthreads();
        if (blk + 1 >= sh_stop) break;     // kept >= POST: rest irrelevant
    }

    if (tid == 0){
        int c = 0;
        for (int ww = 0; ww < MW; ww++){
            kb[ww] = c;
            unsigned long long valid = (ww == MW-1) ? 0xFFFFull : ~0ull;
            c += __popcll((~remv[ww]) & valid);
        }
        kb[MW] = c;
        g_cnt[n] = 0;           // tail: reset candidate counter for next call
    }
    __syncthreads();
    // stable partition: kept (in order) then suppressed (in order) == post top_k
    for (int i = tid; i < PRE; i += 512){
        int ww = i >> 6, b = i & 63;
        unsigned long long valid = (ww == MW-1) ? 0xFFFFull : ~0ull;
        unsigned long long notr = (~remv[ww]) & valid;
        bool keep = (notr >> b) & 1ull;
        unsigned long long below = b ? (notr & ((~0ull) >> (64 - b))) : 0ull;
        int kbelow = kb[ww] + __popcll(below);
        int pos = keep ? kbelow : (kb[MW] + (i - kbelow));
        if (pos < POST){
            float4 bx = g_boxes[n*PRE + i];
            float sc = keep ? g_sc[n*PRE + i] : -1.0f;
            float* op = out + ((size_t)n*POST + pos)*5;
            op[0]=bx.x; op[1]=bx.y; op[2]=bx.z; op[3]=bx.w; op[4]=sc;
        }
    }
}

extern "C" void kernel_launch(void* const* d_in, const int* in_sizes, int n_in,
                              void* d_out, int out_size){
    (void)in_sizes; (void)n_in; (void)out_size;
    const float* logits  = (const float*)d_in[0];
    const float* regs    = (const float*)d_in[1];
    const float* anchors = (const float*)d_in[2];
    const int*   sizes   = (const int*)d_in[3];
    float* out = (float*)d_out;

    dim3 g((AHW4 + 255)/256, NB);
    k_hist<<<g, 256>>>((const float4*)logits);
    k_sortdecode<<<NB, 1024>>>((const float4*)logits, regs, anchors, sizes);
    k_mask<<<dim3(528, NB), 256>>>();
    k_scan<<<NB, 512>>>(out);
}